// round 4
// baseline (speedup 1.0000x reference)
#include <cuda_runtime.h>
#include <cstdint>

#define TT 1024
#define BB 128
#define DD 128
#define HH 512
#define G4 2048   // 4*HH
#define NCTA 128  // persistent grid: 32 h-slices x 4 batch-groups

// Scratch (allocation-free rule: __device__ globals)
static __device__ float g_xg[(size_t)TT * BB * G4];   // [t][b][4H] input-side gates (~1GB)
static __device__ float g_h[2][BB * HH];              // ping-pong hidden state
static __device__ int   g_ctr;                        // global barrier counter

// ---------------------------------------------------------------------------
__global__ void init_state() {
    int i = blockIdx.x * blockDim.x + threadIdx.x;
    if (i < BB * HH) { g_h[0][i] = 0.0f; g_h[1][i] = 0.0f; }
    if (i == 0) g_ctr = 0;
}

// ---------------------------------------------------------------------------
// Phase 1: xg[t][b][g] = sum_d x[b][t][d] * W_ih[g][d] + b_ih[g] + b_hh[g]
__global__ void xg_gemm(const float* __restrict__ x, const float* __restrict__ W_ih,
                        const float* __restrict__ b_ih, const float* __restrict__ b_hh) {
    extern __shared__ float sm[];
    float* As = sm;               // [64][129]
    float* Bs = sm + 64 * 129;    // [64][129]
    const int r0 = blockIdx.x * 64;
    const int n0 = blockIdx.y * 64;
    const int tid = threadIdx.x;

    for (int i = tid; i < 64 * 128; i += 256) {
        int m = i >> 7, k = i & 127;
        As[m * 129 + k] = x[(size_t)(r0 + m) * DD + k];
        Bs[m * 129 + k] = W_ih[(size_t)(n0 + m) * DD + k];
    }
    __syncthreads();

    const int ng = tid & 15, mg = tid >> 4;
    float acc[4][4];
#pragma unroll
    for (int i = 0; i < 4; ++i)
#pragma unroll
        for (int j = 0; j < 4; ++j) acc[i][j] = 0.0f;

#pragma unroll 4
    for (int k = 0; k < 128; ++k) {
        float a[4], b[4];
#pragma unroll
        for (int i = 0; i < 4; ++i) a[i] = As[(mg + 16 * i) * 129 + k];
#pragma unroll
        for (int i = 0; i < 4; ++i) b[i] = Bs[(ng + 16 * i) * 129 + k];
#pragma unroll
        for (int i = 0; i < 4; ++i)
#pragma unroll
            for (int j = 0; j < 4; ++j) acc[i][j] = fmaf(a[i], b[j], acc[i][j]);
    }

#pragma unroll
    for (int mi = 0; mi < 4; ++mi) {
        int r = r0 + mg + 16 * mi;
        int bb = r >> 10;
        int t  = r & 1023;
#pragma unroll
        for (int ni = 0; ni < 4; ++ni) {
            int n = n0 + ng + 16 * ni;
            g_xg[((size_t)t * BB + bb) * G4 + n] = acc[mi][ni] + b_ih[n] + b_hh[n];
        }
    }
}

// ---------------------------------------------------------------------------
__device__ __forceinline__ void cp16(uint32_t dst, const float* src) {
    asm volatile("cp.async.cg.shared.global [%0], [%1], 16;\n" :: "r"(dst), "l"(src));
}
__device__ __forceinline__ void cp_commit() { asm volatile("cp.async.commit_group;\n"); }
__device__ __forceinline__ void cp_wait0()  { asm volatile("cp.async.wait_group 0;\n"); }

// ---------------------------------------------------------------------------
// Phase 2: ONE persistent kernel, 128 CTAs (all co-resident on 148 SMs).
// CTA bx: hs = bx&31 -> h-cols [16*hs, +16); bg = bx>>5 -> batches [32*bg, +32).
// W slice (4 gates x 16 cols x 512) lives in SMEM for the whole kernel.
// Thread (col = tid&15, bt = tid>>4) owns h-col c0+col for batches {b0+bt, b0+bt+16}
// and all 4 gates -> cell state c[2] lives in REGISTERS across all 1024 steps.
// Global barrier: release-RED / acquire-LD on a monotonic counter.
__global__ void __launch_bounds__(256, 1)
lstm_persist(const float* __restrict__ W_hh) {
    extern __shared__ float sm[];
    float* Ws  = sm;              // [64 rows][516]   row = gate*16 + col
    float* hsm = sm + 64 * 516;   // [32 batches][516]
    const int bx = blockIdx.x;
    const int hs = bx & 31, bg = bx >> 5;
    const int c0 = hs * 16, b0 = bg * 32;
    const int tid = threadIdx.x;
    const int col = tid & 15, bt = tid >> 4;
    const uint32_t sm_u32 = (uint32_t)__cvta_generic_to_shared(sm);

    // ---- one-time W load: 64 rows x 512 floats ----
#pragma unroll
    for (int j = 0; j < 32; ++j) {
        int o = tid + 256 * j;            // [0, 8192)
        int row = o >> 7, k4 = o & 127;   // row in [0,64)
        int g = row >> 4, cc = row & 15;
        const float* src = W_hh + ((size_t)(g * HH + c0 + cc) * HH + k4 * 4);
        cp16(sm_u32 + (uint32_t)(row * 2064 + k4 * 16), src);
    }
    cp_commit();
    cp_wait0();
    __syncthreads();

    float cst[2] = {0.0f, 0.0f};   // cell state, register-resident for all steps
    const uint32_t h_u32 = sm_u32 + (uint32_t)(64 * 516 * 4);

    for (int t = 0; t < TT; ++t) {
        const float* __restrict__ hprev = g_h[t & 1];
        float* __restrict__ hnext = g_h[(t + 1) & 1];

        // stage h for this batch group: 32 x 512 floats
#pragma unroll
        for (int j = 0; j < 16; ++j) {
            int o = tid + 256 * j;          // [0, 4096) float4s
            int b = o >> 7, k4 = o & 127;
            cp16(h_u32 + (uint32_t)(b * 2064 + k4 * 16),
                 hprev + (size_t)(b0 + b) * HH + k4 * 4);
        }
        cp_commit();

        // prefetch input-side gates for this thread's outputs (DRAM, long latency)
        float xr[2][4];
        const float* xgb = g_xg + (size_t)t * BB * G4;
#pragma unroll
        for (int bi = 0; bi < 2; ++bi) {
            int b = b0 + bt + 16 * bi;
#pragma unroll
            for (int g = 0; g < 4; ++g)
                xr[bi][g] = __ldcg(xgb + (size_t)b * G4 + g * HH + c0 + col);
        }

        cp_wait0();
        __syncthreads();

        // ---- recurrent GEMM: acc[b][gate] += h . W ----
        float acc[2][4];
#pragma unroll
        for (int i = 0; i < 2; ++i)
#pragma unroll
            for (int j = 0; j < 4; ++j) acc[i][j] = 0.0f;

        const float* w0r = Ws + (0 * 16 + col) * 516;
        const float* w1r = Ws + (1 * 16 + col) * 516;
        const float* w2r = Ws + (2 * 16 + col) * 516;
        const float* w3r = Ws + (3 * 16 + col) * 516;
        const float* h0r = hsm + bt * 516;
        const float* h1r = hsm + (bt + 16) * 516;

#pragma unroll 4
        for (int k4 = 0; k4 < 128; ++k4) {
            float4 w0 = *(const float4*)(w0r + k4 * 4);
            float4 w1 = *(const float4*)(w1r + k4 * 4);
            float4 w2 = *(const float4*)(w2r + k4 * 4);
            float4 w3 = *(const float4*)(w3r + k4 * 4);
            float4 h0 = *(const float4*)(h0r + k4 * 4);
            float4 h1 = *(const float4*)(h1r + k4 * 4);
            acc[0][0] = fmaf(h0.x, w0.x, acc[0][0]); acc[0][0] = fmaf(h0.y, w0.y, acc[0][0]);
            acc[0][0] = fmaf(h0.z, w0.z, acc[0][0]); acc[0][0] = fmaf(h0.w, w0.w, acc[0][0]);
            acc[0][1] = fmaf(h0.x, w1.x, acc[0][1]); acc[0][1] = fmaf(h0.y, w1.y, acc[0][1]);
            acc[0][1] = fmaf(h0.z, w1.z, acc[0][1]); acc[0][1] = fmaf(h0.w, w1.w, acc[0][1]);
            acc[0][2] = fmaf(h0.x, w2.x, acc[0][2]); acc[0][2] = fmaf(h0.y, w2.y, acc[0][2]);
            acc[0][2] = fmaf(h0.z, w2.z, acc[0][2]); acc[0][2] = fmaf(h0.w, w2.w, acc[0][2]);
            acc[0][3] = fmaf(h0.x, w3.x, acc[0][3]); acc[0][3] = fmaf(h0.y, w3.y, acc[0][3]);
            acc[0][3] = fmaf(h0.z, w3.z, acc[0][3]); acc[0][3] = fmaf(h0.w, w3.w, acc[0][3]);
            acc[1][0] = fmaf(h1.x, w0.x, acc[1][0]); acc[1][0] = fmaf(h1.y, w0.y, acc[1][0]);
            acc[1][0] = fmaf(h1.z, w0.z, acc[1][0]); acc[1][0] = fmaf(h1.w, w0.w, acc[1][0]);
            acc[1][1] = fmaf(h1.x, w1.x, acc[1][1]); acc[1][1] = fmaf(h1.y, w1.y, acc[1][1]);
            acc[1][1] = fmaf(h1.z, w1.z, acc[1][1]); acc[1][1] = fmaf(h1.w, w1.w, acc[1][1]);
            acc[1][2] = fmaf(h1.x, w2.x, acc[1][2]); acc[1][2] = fmaf(h1.y, w2.y, acc[1][2]);
            acc[1][2] = fmaf(h1.z, w2.z, acc[1][2]); acc[1][2] = fmaf(h1.w, w2.w, acc[1][2]);
            acc[1][3] = fmaf(h1.x, w3.x, acc[1][3]); acc[1][3] = fmaf(h1.y, w3.y, acc[1][3]);
            acc[1][3] = fmaf(h1.z, w3.z, acc[1][3]); acc[1][3] = fmaf(h1.w, w3.w, acc[1][3]);
        }

        // ---- cell update (thread-local) + h write ----
#pragma unroll
        for (int bi = 0; bi < 2; ++bi) {
            int b = b0 + bt + 16 * bi;
            float pi = acc[bi][0] + xr[bi][0];
            float pf = acc[bi][1] + xr[bi][1];
            float pg = acc[bi][2] + xr[bi][2];
            float po = acc[bi][3] + xr[bi][3];
            float ig = 1.0f / (1.0f + expf(-pi));
            float fg = 1.0f / (1.0f + expf(-pf));
            float gg = tanhf(pg);
            float og = 1.0f / (1.0f + expf(-po));
            float c  = fg * cst[bi] + ig * gg;
            cst[bi] = c;
            hnext[(size_t)b * HH + c0 + col] = og * tanhf(c);
        }

        // ---- global barrier (monotonic counter) ----
        __syncthreads();                 // all h stores in CTA issued
        if (tid == 0) {
            __threadfence();
            int* ctr = &g_ctr;
            asm volatile("red.release.gpu.global.add.s32 [%0], 1;" :: "l"(ctr) : "memory");
            const int target = NCTA * (t + 1);
            int v;
            do {
                asm volatile("ld.acquire.gpu.global.s32 %0, [%1];" : "=r"(v) : "l"(ctr) : "memory");
            } while (v < target);
        }
        __syncthreads();
    }
}

// ---------------------------------------------------------------------------
// Phase 3: out[b] = sigmoid(h_last . W_fc + b_fc). t=1023 wrote g_h[0].
__global__ void fc_out(const float* __restrict__ W_fc, const float* __restrict__ b_fc,
                       float* __restrict__ out) {
    __shared__ float red[128];
    const int b = blockIdx.x, tid = threadIdx.x;
    const float* h = g_h[0] + b * HH;
    float s = 0.0f;
#pragma unroll
    for (int k = tid; k < HH; k += 128) s = fmaf(h[k], W_fc[k], s);
    red[tid] = s;
    __syncthreads();
    for (int off = 64; off > 0; off >>= 1) {
        if (tid < off) red[tid] += red[tid + off];
        __syncthreads();
    }
    if (tid == 0) out[b] = 1.0f / (1.0f + expf(-(red[0] + b_fc[0])));
}

// ---------------------------------------------------------------------------
extern "C" void kernel_launch(void* const* d_in, const int* in_sizes, int n_in,
                              void* d_out, int out_size) {
    const float* x    = (const float*)d_in[0];
    const float* W_ih = (const float*)d_in[1];
    const float* W_hh = (const float*)d_in[2];
    const float* b_ih = (const float*)d_in[3];
    const float* b_hh = (const float*)d_in[4];
    const float* W_fc = (const float*)d_in[5];
    const float* b_fc = (const float*)d_in[6];
    float* out = (float*)d_out;

    cudaFuncSetAttribute(xg_gemm,      cudaFuncAttributeMaxDynamicSharedMemorySize, 66048);
    cudaFuncSetAttribute(lstm_persist, cudaFuncAttributeMaxDynamicSharedMemorySize, 198144);

    init_state<<<(BB * HH + 255) / 256, 256>>>();
    xg_gemm<<<dim3((BB * TT) / 64, G4 / 64), 256, 66048>>>(x, W_ih, b_ih, b_hh);
    lstm_persist<<<NCTA, 256, 198144>>>(W_hh);
    fc_out<<<BB, 128>>>(W_fc, b_fc, out);
}

// round 11
// speedup vs baseline: 1.7890x; 1.7890x over previous
#include <cuda_runtime.h>
#include <cuda_bf16.h>
#include <cstdint>

#define TT 1024
#define BB 128
#define DD 128
#define HH 512
#define G4 2048   // 4*HH
#define NCTA 128  // persistent grid: 32 col-slices x 4 batch-groups

// SMEM byte offsets (rows padded to 1040 B = 520 bf16 -> conflict-free LDSM)
#define WHI 0                       // [64][520] bf16  W hi
#define WLO 66560                   // [64][520] bf16  W lo
#define HHI 133120                  // [32][520] bf16  h hi
#define HLO 166400                  // [32][520] bf16  h lo
#define DSM 199680                  // [32][68] fp32   D tile
#define SMEM_BYTES 208384

// Scratch (allocation-free rule: __device__ globals)
static __device__ float g_xg[(size_t)TT * BB * G4];   // [t][b][4H] input-side gates (~1GB)
static __device__ float g_h[2][BB * HH];              // ping-pong hidden state
static __device__ int   g_ctr;                        // global barrier counter

// ---------------------------------------------------------------------------
__global__ void init_state() {
    int i = blockIdx.x * blockDim.x + threadIdx.x;
    if (i < BB * HH) { g_h[0][i] = 0.0f; g_h[1][i] = 0.0f; }
    if (i == 0) g_ctr = 0;
}

// ---------------------------------------------------------------------------
// Phase 1: xg[t][b][g] = sum_d x[b][t][d] * W_ih[g][d] + b_ih[g] + b_hh[g]
__global__ void xg_gemm(const float* __restrict__ x, const float* __restrict__ W_ih,
                        const float* __restrict__ b_ih, const float* __restrict__ b_hh) {
    extern __shared__ float sm[];
    float* As = sm;               // [64][129]
    float* Bs = sm + 64 * 129;    // [64][129]
    const int r0 = blockIdx.x * 64;
    const int n0 = blockIdx.y * 64;
    const int tid = threadIdx.x;

    for (int i = tid; i < 64 * 128; i += 256) {
        int m = i >> 7, k = i & 127;
        As[m * 129 + k] = x[(size_t)(r0 + m) * DD + k];
        Bs[m * 129 + k] = W_ih[(size_t)(n0 + m) * DD + k];
    }
    __syncthreads();

    const int ng = tid & 15, mg = tid >> 4;
    float acc[4][4];
#pragma unroll
    for (int i = 0; i < 4; ++i)
#pragma unroll
        for (int j = 0; j < 4; ++j) acc[i][j] = 0.0f;

#pragma unroll 4
    for (int k = 0; k < 128; ++k) {
        float a[4], b[4];
#pragma unroll
        for (int i = 0; i < 4; ++i) a[i] = As[(mg + 16 * i) * 129 + k];
#pragma unroll
        for (int i = 0; i < 4; ++i) b[i] = Bs[(ng + 16 * i) * 129 + k];
#pragma unroll
        for (int i = 0; i < 4; ++i)
#pragma unroll
            for (int j = 0; j < 4; ++j) acc[i][j] = fmaf(a[i], b[j], acc[i][j]);
    }

#pragma unroll
    for (int mi = 0; mi < 4; ++mi) {
        int r = r0 + mg + 16 * mi;
        int bb = r >> 10;
        int t  = r & 1023;
#pragma unroll
        for (int ni = 0; ni < 4; ++ni) {
            int n = n0 + ng + 16 * ni;
            g_xg[((size_t)t * BB + bb) * G4 + n] = acc[mi][ni] + b_ih[n] + b_hh[n];
        }
    }
}

// ---------------------------------------------------------------------------
// mma.sync / ldmatrix helpers (sm_80+ baseline PTX; compiles for plain sm_103)
// ---------------------------------------------------------------------------
#define LDSM_X4(r0, r1, r2, r3, a) \
    asm volatile("ldmatrix.sync.aligned.m8n8.x4.shared.b16 {%0,%1,%2,%3}, [%4];" \
                 : "=r"(r0), "=r"(r1), "=r"(r2), "=r"(r3) : "r"(a))
#define LDSM_X2(r0, r1, a) \
    asm volatile("ldmatrix.sync.aligned.m8n8.x2.shared.b16 {%0,%1}, [%2];" \
                 : "=r"(r0), "=r"(r1) : "r"(a))
#define MMA16816(c, a0, a1, a2, a3, b0, b1) \
    asm volatile("mma.sync.aligned.m16n8k16.row.col.f32.bf16.bf16.f32 " \
                 "{%0,%1,%2,%3}, {%4,%5,%6,%7}, {%8,%9}, {%0,%1,%2,%3};" \
                 : "+f"((c)[0]), "+f"((c)[1]), "+f"((c)[2]), "+f"((c)[3]) \
                 : "r"(a0), "r"(a1), "r"(a2), "r"(a3), "r"(b0), "r"(b1))

__device__ __forceinline__ uint32_t pk_hi(float x, float y, float& rx, float& ry) {
    __nv_bfloat16 hx = __float2bfloat16_rn(x), hy = __float2bfloat16_rn(y);
    rx = x - __bfloat162float(hx);
    ry = y - __bfloat162float(hy);
    return ((uint32_t)__bfloat16_as_ushort(hy) << 16) | __bfloat16_as_ushort(hx);
}
__device__ __forceinline__ uint32_t pk(float x, float y) {
    __nv_bfloat16 hx = __float2bfloat16_rn(x), hy = __float2bfloat16_rn(y);
    return ((uint32_t)__bfloat16_as_ushort(hy) << 16) | __bfloat16_as_ushort(hx);
}

// ---------------------------------------------------------------------------
// Phase 2: persistent HMMA LSTM. CTA bx: hs=bx&31 -> h-cols [16hs,+16);
// bg=bx>>5 -> batches [32bg,+32). Per step CTA computes
// D[32 batch, 64 gate-rows] = h . Wslice^T, gate-row n = gate(n>>4), col(n&15).
// bf16 3-term split: D = Ahi*Bhi + Alo*Bhi + Ahi*Blo (fp32 accum).
// Warp w: n-tile n0=8w (fixed), both 16-row m-tiles. Cell state in registers.
__global__ void __launch_bounds__(256, 1)
lstm_mma(const float* __restrict__ W_hh) {
    extern __shared__ char smc[];
    const uint32_t sb = (uint32_t)__cvta_generic_to_shared(smc);
    const int tid = threadIdx.x, wid = tid >> 5, lane = tid & 31;
    const int hs = blockIdx.x & 31, bg = blockIdx.x >> 5;
    const int c0 = hs * 16, b0g = bg * 32;

    // ---- one-time W slice load -> bf16 hi/lo ----
    for (int p = tid; p < 64 * 256; p += 256) {
        int n = p >> 8, kw = p & 255, k = kw * 2;
        int grow = (n >> 4) * HH + c0 + (n & 15);
        float w0 = W_hh[(size_t)grow * HH + k];
        float w1 = W_hh[(size_t)grow * HH + k + 1];
        float r0, r1;
        uint32_t hwv = pk_hi(w0, w1, r0, r1);
        *(uint32_t*)(smc + WHI + n * 1040 + kw * 4) = hwv;
        *(uint32_t*)(smc + WLO + n * 1040 + kw * 4) = pk(r0, r1);
    }
    __syncthreads();

    // ldmatrix base addresses (k0 = 0)
    const uint32_t aAh0_b = sb + HHI + (uint32_t)((lane & 15) * 1040) + ((lane & 16) ? 16u : 0u);
    const uint32_t aAh1_b = aAh0_b + 16 * 1040;
    const uint32_t aAl0_b = aAh0_b + (HLO - HHI);
    const uint32_t aAl1_b = aAl0_b + 16 * 1040;
    const uint32_t aBh_b  = sb + WHI + (uint32_t)((wid * 8 + (lane & 7)) * 1040) + ((lane & 8) ? 16u : 0u);
    const uint32_t aBl_b  = aBh_b + (WLO - WHI);

    const int col = tid & 15, bt = tid >> 4;   // epilogue ownership
    float* Drow = (float*)(smc + DSM);
    float cst[2] = {0.0f, 0.0f};

    for (int t = 0; t < TT; ++t) {
        const float* __restrict__ hprev = g_h[t & 1];
        float* __restrict__ hnext = g_h[(t + 1) & 1];

        // ---- stage h: 32 batches x 512, fp32(L2) -> bf16 hi/lo in SMEM ----
        const float4* h4 = (const float4*)(hprev + (size_t)b0g * HH);
#pragma unroll
        for (int i = 0; i < 16; ++i) {
            int o = tid + 256 * i;
            int b = o >> 7, k4 = o & 127;
            float4 v = __ldcg(h4 + b * 128 + k4);
            float rx, ry, rz, rw;
            uint32_t h01 = pk_hi(v.x, v.y, rx, ry);
            uint32_t h23 = pk_hi(v.z, v.w, rz, rw);
            *(uint32_t*)(smc + HHI + b * 1040 + k4 * 8)     = h01;
            *(uint32_t*)(smc + HHI + b * 1040 + k4 * 8 + 4) = h23;
            *(uint32_t*)(smc + HLO + b * 1040 + k4 * 8)     = pk(rx, ry);
            *(uint32_t*)(smc + HLO + b * 1040 + k4 * 8 + 4) = pk(rz, rw);
        }

        // ---- prefetch input-side gates (DRAM latency hidden under MMA) ----
        float xr[2][4];
        const float* xgp = g_xg + ((size_t)t * BB + b0g) * G4;
#pragma unroll
        for (int bi = 0; bi < 2; ++bi) {
            int l = bt + 16 * bi;
#pragma unroll
            for (int g = 0; g < 4; ++g)
                xr[bi][g] = __ldcg(xgp + (size_t)l * G4 + g * HH + c0 + col);
        }
        __syncthreads();

        // ---- tensor-core K loop: 32 x k16, 6 LDSM + 6 MMA per iter ----
        float acc0[4] = {0, 0, 0, 0}, acc1[4] = {0, 0, 0, 0};
        uint32_t aAh0 = aAh0_b, aAh1 = aAh1_b, aAl0 = aAl0_b, aAl1 = aAl1_b;
        uint32_t aBh = aBh_b, aBl = aBl_b;
#pragma unroll 4
        for (int k = 0; k < 32; ++k) {
            uint32_t ah0[4], ah1[4], al0[4], al1[4], bh[2], bl[2];
            LDSM_X4(ah0[0], ah0[1], ah0[2], ah0[3], aAh0);
            LDSM_X4(ah1[0], ah1[1], ah1[2], ah1[3], aAh1);
            LDSM_X4(al0[0], al0[1], al0[2], al0[3], aAl0);
            LDSM_X4(al1[0], al1[1], al1[2], al1[3], aAl1);
            LDSM_X2(bh[0], bh[1], aBh);
            LDSM_X2(bl[0], bl[1], aBl);
            MMA16816(acc0, ah0[0], ah0[1], ah0[2], ah0[3], bh[0], bh[1]);
            MMA16816(acc1, ah1[0], ah1[1], ah1[2], ah1[3], bh[0], bh[1]);
            MMA16816(acc0, al0[0], al0[1], al0[2], al0[3], bh[0], bh[1]);
            MMA16816(acc1, al1[0], al1[1], al1[2], al1[3], bh[0], bh[1]);
            MMA16816(acc0, ah0[0], ah0[1], ah0[2], ah0[3], bl[0], bl[1]);
            MMA16816(acc1, ah1[0], ah1[1], ah1[2], ah1[3], bl[0], bl[1]);
            aAh0 += 32; aAh1 += 32; aAl0 += 32; aAl1 += 32; aBh += 32; aBl += 32;
        }

        // ---- D -> SMEM ----
        {
            int r = lane >> 2, cn = (wid * 8) + (lane & 3) * 2;
            *(float2*)&Drow[(r     ) * 68 + cn] = make_float2(acc0[0], acc0[1]);
            *(float2*)&Drow[(r +  8) * 68 + cn] = make_float2(acc0[2], acc0[3]);
            *(float2*)&Drow[(r + 16) * 68 + cn] = make_float2(acc1[0], acc1[1]);
            *(float2*)&Drow[(r + 24) * 68 + cn] = make_float2(acc1[2], acc1[3]);
        }
        __syncthreads();

        // ---- cell update: thread owns col (c0+col), batches {bt, bt+16} ----
#pragma unroll
        for (int bi = 0; bi < 2; ++bi) {
            int l = bt + 16 * bi;
            float pi = Drow[l * 68 +  0 + col] + xr[bi][0];
            float pf = Drow[l * 68 + 16 + col] + xr[bi][1];
            float pg = Drow[l * 68 + 32 + col] + xr[bi][2];
            float po = Drow[l * 68 + 48 + col] + xr[bi][3];
            float ig = 1.0f / (1.0f + expf(-pi));
            float fg = 1.0f / (1.0f + expf(-pf));
            float gg = tanhf(pg);
            float og = 1.0f / (1.0f + expf(-po));
            float c  = fg * cst[bi] + ig * gg;
            cst[bi] = c;
            hnext[(size_t)(b0g + l) * HH + c0 + col] = og * tanhf(c);
        }

        // ---- global barrier ----
        __syncthreads();
        if (tid == 0) {
            __threadfence();
            int* ctr = &g_ctr;
            asm volatile("red.release.gpu.global.add.s32 [%0], 1;" :: "l"(ctr) : "memory");
            const int target = NCTA * (t + 1);
            int v;
            do {
                asm volatile("ld.acquire.gpu.global.s32 %0, [%1];" : "=r"(v) : "l"(ctr) : "memory");
            } while (v < target);
        }
        __syncthreads();
    }
}

// ---------------------------------------------------------------------------
// Phase 3: out[b] = sigmoid(h_last . W_fc + b_fc). t=1023 wrote g_h[0].
__global__ void fc_out(const float* __restrict__ W_fc, const float* __restrict__ b_fc,
                       float* __restrict__ out) {
    __shared__ float red[128];
    const int b = blockIdx.x, tid = threadIdx.x;
    const float* h = g_h[0] + b * HH;
    float s = 0.0f;
#pragma unroll
    for (int k = tid; k < HH; k += 128) s = fmaf(h[k], W_fc[k], s);
    red[tid] = s;
    __syncthreads();
    for (int off = 64; off > 0; off >>= 1) {
        if (tid < off) red[tid] += red[tid + off];
        __syncthreads();
    }
    if (tid == 0) out[b] = 1.0f / (1.0f + expf(-(red[0] + b_fc[0])));
}

// ---------------------------------------------------------------------------
extern "C" void kernel_launch(void* const* d_in, const int* in_sizes, int n_in,
                              void* d_out, int out_size) {
    const float* x    = (const float*)d_in[0];
    const float* W_ih = (const float*)d_in[1];
    const float* W_hh = (const float*)d_in[2];
    const float* b_ih = (const float*)d_in[3];
    const float* b_hh = (const float*)d_in[4];
    const float* W_fc = (const float*)d_in[5];
    const float* b_fc = (const float*)d_in[6];
    float* out = (float*)d_out;

    cudaFuncSetAttribute(xg_gemm,  cudaFuncAttributeMaxDynamicSharedMemorySize, 66048);
    cudaFuncSetAttribute(lstm_mma, cudaFuncAttributeMaxDynamicSharedMemorySize, SMEM_BYTES);

    init_state<<<(BB * HH + 255) / 256, 256>>>();
    xg_gemm<<<dim3((BB * TT) / 64, G4 / 64), 256, 66048>>>(x, W_ih, b_ih, b_hh);
    lstm_mma<<<NCTA, 256, SMEM_BYTES>>>(W_hh);
    fc_out<<<BB, 128>>>(W_fc, b_fc, out);
}

// round 13
// speedup vs baseline: 2.5251x; 1.4115x over previous
#include <cuda_runtime.h>
#include <cuda_bf16.h>
#include <cstdint>

#define TT 1024
#define BB 128
#define DD 128
#define HH 512
#define G4 2048   // 4*HH
#define NCTA 128  // persistent grid: 32 col-slices x 4 batch-groups

// ---- phase-2 SMEM layout (rows padded to 1040 B -> conflict-free ldmatrix) ----
#define WHI 0                       // [64][520] bf16  W hi
#define WLO 66560                   // [64][520] bf16  W lo
#define HHI 133120                  // [32][520] bf16  h hi
#define HLO 166400                  // [32][520] bf16  h lo
#define DSM 199680                  // [32][68] fp32   D tile
#define SMEM_BYTES 208384

// ---- phase-1 SMEM layout (rows padded to 272 B) ----
#define XHI1 0                      // [128][136] bf16 x hi
#define XLO1 34816                  // [128][136] bf16 x lo
#define WHI1 69632                  // [128][136] bf16 W hi
#define WLO1 104448                 // [128][136] bf16 W lo
#define BIAS1 139264                // [128] f32
#define SMEM1_BYTES 139776
// D overlay [128][132] f32 = 67584 bytes over XHI1/XLO1 after MMA

// Scratch (allocation-free rule: __device__ globals)
static __device__ float g_xg[(size_t)TT * BB * G4];        // [t][b][4H] (~1GB)
static __device__ __nv_bfloat16 g_hh[2][BB * HH];          // h hi plane (ping-pong)
static __device__ __nv_bfloat16 g_hl[2][BB * HH];          // h lo plane
static __device__ int g_ctr4[128];                         // 4 group barriers, 128B apart

// ---------------------------------------------------------------------------
__global__ void init_state() {
    int i = blockIdx.x * blockDim.x + threadIdx.x;
    if (i < BB * HH) {
        g_hh[0][i] = __float2bfloat16_rn(0.0f); g_hl[0][i] = __float2bfloat16_rn(0.0f);
        g_hh[1][i] = __float2bfloat16_rn(0.0f); g_hl[1][i] = __float2bfloat16_rn(0.0f);
    }
    if (i < 128) g_ctr4[i] = 0;
}

// ---------------------------------------------------------------------------
// mma.sync / ldmatrix helpers (sm_80+ baseline PTX)
// ---------------------------------------------------------------------------
#define LDSM_X4(r0, r1, r2, r3, a) \
    asm volatile("ldmatrix.sync.aligned.m8n8.x4.shared.b16 {%0,%1,%2,%3}, [%4];" \
                 : "=r"(r0), "=r"(r1), "=r"(r2), "=r"(r3) : "r"(a))
#define LDSM_X2(r0, r1, a) \
    asm volatile("ldmatrix.sync.aligned.m8n8.x2.shared.b16 {%0,%1}, [%2];" \
                 : "=r"(r0), "=r"(r1) : "r"(a))
#define MMA16816(c, a0, a1, a2, a3, b0, b1) \
    asm volatile("mma.sync.aligned.m16n8k16.row.col.f32.bf16.bf16.f32 " \
                 "{%0,%1,%2,%3}, {%4,%5,%6,%7}, {%8,%9}, {%0,%1,%2,%3};" \
                 : "+f"((c)[0]), "+f"((c)[1]), "+f"((c)[2]), "+f"((c)[3]) \
                 : "r"(a0), "r"(a1), "r"(a2), "r"(a3), "r"(b0), "r"(b1))

__device__ __forceinline__ void cp16(uint32_t dst, const void* src) {
    asm volatile("cp.async.cg.shared.global [%0], [%1], 16;\n" :: "r"(dst), "l"(src));
}
__device__ __forceinline__ void cp_commit() { asm volatile("cp.async.commit_group;\n"); }
__device__ __forceinline__ void cp_wait0()  { asm volatile("cp.async.wait_group 0;\n"); }

__device__ __forceinline__ uint32_t pk_hi(float x, float y, float& rx, float& ry) {
    __nv_bfloat16 hx = __float2bfloat16_rn(x), hy = __float2bfloat16_rn(y);
    rx = x - __bfloat162float(hx);
    ry = y - __bfloat162float(hy);
    return ((uint32_t)__bfloat16_as_ushort(hy) << 16) | __bfloat16_as_ushort(hx);
}
__device__ __forceinline__ uint32_t pk(float x, float y) {
    __nv_bfloat16 hx = __float2bfloat16_rn(x), hy = __float2bfloat16_rn(y);
    return ((uint32_t)__bfloat16_as_ushort(hy) << 16) | __bfloat16_as_ushort(hx);
}

// ---------------------------------------------------------------------------
// Phase 1 (HMMA): xg[t][b][n] = sum_d x[b,t,d]*W_ih[n,d] + b_ih[n] + b_hh[n]
// CTA tile: M=128 x-rows, N=128 gates, K=128. 3-term bf16 split.
// Warp (wm=wid&1, wn=wid>>1): m16 tiles {4wm..4wm+3}, n8 tiles {4wn..4wn+3}.
__global__ void __launch_bounds__(256, 1)
xg_hmma(const float* __restrict__ x, const float* __restrict__ W_ih,
        const float* __restrict__ b_ih, const float* __restrict__ b_hh) {
    extern __shared__ char smc[];
    const uint32_t sb = (uint32_t)__cvta_generic_to_shared(smc);
    const int tid = threadIdx.x, wid = tid >> 5, lane = tid & 31;
    const int r0 = blockIdx.x * 128, n0 = blockIdx.y * 128;

    // ---- stage x and W tiles -> bf16 hi/lo ----
#pragma unroll
    for (int i = 0; i < 16; ++i) {
        int o = tid + 256 * i;             // float4 index [0,4096)
        int row = o >> 5, q = o & 31;
        float4 vx = *(const float4*)(x + (size_t)(r0 + row) * DD + q * 4);
        float4 vw = *(const float4*)(W_ih + (size_t)(n0 + row) * DD + q * 4);
        float rx, ry, rz, rw;
        uint32_t xh01 = pk_hi(vx.x, vx.y, rx, ry);
        uint32_t xh23 = pk_hi(vx.z, vx.w, rz, rw);
        *(uint32_t*)(smc + XHI1 + row * 272 + q * 8)     = xh01;
        *(uint32_t*)(smc + XHI1 + row * 272 + q * 8 + 4) = xh23;
        *(uint32_t*)(smc + XLO1 + row * 272 + q * 8)     = pk(rx, ry);
        *(uint32_t*)(smc + XLO1 + row * 272 + q * 8 + 4) = pk(rz, rw);
        uint32_t wh01 = pk_hi(vw.x, vw.y, rx, ry);
        uint32_t wh23 = pk_hi(vw.z, vw.w, rz, rw);
        *(uint32_t*)(smc + WHI1 + row * 272 + q * 8)     = wh01;
        *(uint32_t*)(smc + WHI1 + row * 272 + q * 8 + 4) = wh23;
        *(uint32_t*)(smc + WLO1 + row * 272 + q * 8)     = pk(rx, ry);
        *(uint32_t*)(smc + WLO1 + row * 272 + q * 8 + 4) = pk(rz, rw);
    }
    if (tid < 128) *(float*)(smc + BIAS1 + tid * 4) = b_ih[n0 + tid] + b_hh[n0 + tid];
    __syncthreads();

    const int wm = wid & 1, wn = wid >> 1;   // wn in 0..3
    float acc[4][4][4];
#pragma unroll
    for (int a = 0; a < 4; ++a)
#pragma unroll
        for (int b = 0; b < 4; ++b)
#pragma unroll
            for (int c = 0; c < 4; ++c) acc[a][b][c] = 0.0f;

    uint32_t aA = sb + XHI1 + (uint32_t)((wm * 64 + (lane & 15)) * 272) + ((lane & 16) ? 16u : 0u);
    uint32_t aB = sb + WHI1 + (uint32_t)((wn * 32 + (lane & 7)) * 272) + ((lane & 8) ? 16u : 0u);

#pragma unroll 2
    for (int k = 0; k < 8; ++k) {
        uint32_t ah[4][4], al[4][4], bh[4][2], bl[4][2];
#pragma unroll
        for (int mj = 0; mj < 4; ++mj) {
            LDSM_X4(ah[mj][0], ah[mj][1], ah[mj][2], ah[mj][3], aA + mj * 4352u);
            LDSM_X4(al[mj][0], al[mj][1], al[mj][2], al[mj][3], aA + mj * 4352u + 34816u);
        }
#pragma unroll
        for (int nj = 0; nj < 4; ++nj) {
            LDSM_X2(bh[nj][0], bh[nj][1], aB + nj * 2176u);
            LDSM_X2(bl[nj][0], bl[nj][1], aB + nj * 2176u + 34816u);
        }
#pragma unroll
        for (int mj = 0; mj < 4; ++mj)
#pragma unroll
            for (int nj = 0; nj < 4; ++nj) {
                MMA16816(acc[mj][nj], ah[mj][0], ah[mj][1], ah[mj][2], ah[mj][3], bh[nj][0], bh[nj][1]);
                MMA16816(acc[mj][nj], al[mj][0], al[mj][1], al[mj][2], al[mj][3], bh[nj][0], bh[nj][1]);
                MMA16816(acc[mj][nj], ah[mj][0], ah[mj][1], ah[mj][2], ah[mj][3], bl[nj][0], bl[nj][1]);
            }
        aA += 32; aB += 32;
    }
    __syncthreads();   // x/W reads done; D overlays x region

    float* Dsm = (float*)smc;
    {
        int rr = wm * 64 + (lane >> 2), cb = wn * 32 + (lane & 3) * 2;
#pragma unroll
        for (int mj = 0; mj < 4; ++mj)
#pragma unroll
            for (int nj = 0; nj < 4; ++nj) {
                *(float2*)&Dsm[(rr + mj * 16) * 132 + cb + nj * 8]     = make_float2(acc[mj][nj][0], acc[mj][nj][1]);
                *(float2*)&Dsm[(rr + mj * 16 + 8) * 132 + cb + nj * 8] = make_float2(acc[mj][nj][2], acc[mj][nj][3]);
            }
    }
    __syncthreads();

    const float* bias = (const float*)(smc + BIAS1);
#pragma unroll
    for (int i = 0; i < 16; ++i) {
        int o = tid + 256 * i;
        int row = o >> 5, q = o & 31;
        float4 v;
        v.x = Dsm[row * 132 + q * 4]     + bias[q * 4];
        v.y = Dsm[row * 132 + q * 4 + 1] + bias[q * 4 + 1];
        v.z = Dsm[row * 132 + q * 4 + 2] + bias[q * 4 + 2];
        v.w = Dsm[row * 132 + q * 4 + 3] + bias[q * 4 + 3];
        int r = r0 + row;
        int b = r >> 10, tt = r & 1023;
        *(float4*)(g_xg + ((size_t)tt * BB + b) * G4 + n0 + q * 4) = v;
    }
}

// ---------------------------------------------------------------------------
// Phase 2: persistent HMMA LSTM. CTA bx: hs=bx&31 -> h-cols [16hs,+16);
// bg=bx>>5 -> batches [32bg,+32). Warps 0-3 compute (warp = m16 x n32),
// warps 4-7 assist staging/epilogue only. h exchanged as pre-split bf16 hi/lo
// planes staged via cp.async. 4 independent per-bg barriers.
__global__ void __launch_bounds__(256, 1)
lstm_mma(const float* __restrict__ W_hh) {
    extern __shared__ char smc[];
    const uint32_t sb = (uint32_t)__cvta_generic_to_shared(smc);
    const int tid = threadIdx.x, wid = tid >> 5, lane = tid & 31;
    const int hs = blockIdx.x & 31, bg = blockIdx.x >> 5;
    const int c0 = hs * 16, b0g = bg * 32;

    // ---- one-time W slice load -> bf16 hi/lo (row n = gate(n>>4), col(n&15)) ----
    for (int p = tid; p < 64 * 256; p += 256) {
        int n = p >> 8, kw = p & 255, k = kw * 2;
        int grow = (n >> 4) * HH + c0 + (n & 15);
        float w0 = W_hh[(size_t)grow * HH + k];
        float w1 = W_hh[(size_t)grow * HH + k + 1];
        float r0, r1;
        uint32_t hwv = pk_hi(w0, w1, r0, r1);
        *(uint32_t*)(smc + WHI + n * 1040 + kw * 4) = hwv;
        *(uint32_t*)(smc + WLO + n * 1040 + kw * 4) = pk(r0, r1);
    }
    __syncthreads();

    const int col = tid & 15, bt = tid >> 4;   // epilogue ownership
    float* Drow = (float*)(smc + DSM);
    float cst[2] = {0.0f, 0.0f};

    // initial xg prefetch (t = 0)
    float xr[2][4], xn[2][4];
    {
        const float* xgp = g_xg + (size_t)b0g * G4;
#pragma unroll
        for (int bi = 0; bi < 2; ++bi) {
            int l = bt + 16 * bi;
#pragma unroll
            for (int g = 0; g < 4; ++g)
                xr[bi][g] = __ldcg(xgp + (size_t)l * G4 + g * HH + c0 + col);
        }
    }

    for (int t = 0; t < TT; ++t) {
        // ---- stage h(t) bf16 hi/lo via cp.async (L2, no convert) ----
        const __nv_bfloat16* hhp = g_hh[t & 1];
        const __nv_bfloat16* hlp = g_hl[t & 1];
#pragma unroll
        for (int i = 0; i < 16; ++i) {
            int c = tid + 256 * i;              // [0,4096) 16B chunks
            int pl = c >> 11, b = (c >> 6) & 31, kc = c & 63;
            const __nv_bfloat16* src = (pl ? hlp : hhp) + (size_t)(b0g + b) * HH + kc * 8;
            uint32_t dst = sb + (pl ? HLO : HHI) + (uint32_t)(b * 1040 + kc * 16);
            cp16(dst, src);
        }
        cp_commit();

        // ---- prefetch xg(t+1) while cp.async + MMA run ----
        {
            int tn = (t + 1 < TT) ? t + 1 : t;
            const float* xgp = g_xg + ((size_t)tn * BB + b0g) * G4;
#pragma unroll
            for (int bi = 0; bi < 2; ++bi) {
                int l = bt + 16 * bi;
#pragma unroll
                for (int g = 0; g < 4; ++g)
                    xn[bi][g] = __ldcg(xgp + (size_t)l * G4 + g * HH + c0 + col);
            }
        }

        cp_wait0();
        __syncthreads();

        // ---- tensor-core loop: 4 compute warps, warp = m16(wm) x n32(wn) ----
        if (wid < 4) {
            const int wm = wid & 1, wn = wid >> 1;
            float acc[4][4];
#pragma unroll
            for (int a = 0; a < 4; ++a)
#pragma unroll
                for (int b = 0; b < 4; ++b) acc[a][b] = 0.0f;

            uint32_t aA = sb + HHI + (uint32_t)((wm * 16 + (lane & 15)) * 1040) + ((lane & 16) ? 16u : 0u);
            uint32_t aB = sb + WHI + (uint32_t)((wn * 32 + (lane & 7)) * 1040) + (uint32_t)((lane >> 3) * 16);

#pragma unroll 2
            for (int k = 0; k < 16; ++k) {     // k32 blocks
                uint32_t ahA[4], ahB[4], alA[4], alB[4];
                LDSM_X4(ahA[0], ahA[1], ahA[2], ahA[3], aA);
                LDSM_X4(ahB[0], ahB[1], ahB[2], ahB[3], aA + 32u);
                LDSM_X4(alA[0], alA[1], alA[2], alA[3], aA + 33280u);
                LDSM_X4(alB[0], alB[1], alB[2], alB[3], aA + 33280u + 32u);
#pragma unroll
                for (int nj = 0; nj < 4; ++nj) {
                    uint32_t bh[4], bl[4];
                    LDSM_X4(bh[0], bh[1], bh[2], bh[3], aB + nj * 8320u);
                    LDSM_X4(bl[0], bl[1], bl[2], bl[3], aB + nj * 8320u + 66560u);
                    MMA16816(acc[nj], ahA[0], ahA[1], ahA[2], ahA[3], bh[0], bh[1]);
                    MMA16816(acc[nj], alA[0], alA[1], alA[2], alA[3], bh[0], bh[1]);
                    MMA16816(acc[nj], ahA[0], ahA[1], ahA[2], ahA[3], bl[0], bl[1]);
                    MMA16816(acc[nj], ahB[0], ahB[1], ahB[2], ahB[3], bh[2], bh[3]);
                    MMA16816(acc[nj], alB[0], alB[1], alB[2], alB[3], bh[2], bh[3]);
                    MMA16816(acc[nj], ahB[0], ahB[1], ahB[2], ahB[3], bl[2], bl[3]);
                }
                aA += 64; aB += 64;
            }
            int rr = wm * 16 + (lane >> 2), cb = wn * 32 + (lane & 3) * 2;
#pragma unroll
            for (int nj = 0; nj < 4; ++nj) {
                *(float2*)&Drow[rr * 68 + cb + nj * 8]       = make_float2(acc[nj][0], acc[nj][1]);
                *(float2*)&Drow[(rr + 8) * 68 + cb + nj * 8] = make_float2(acc[nj][2], acc[nj][3]);
            }
        }
        __syncthreads();

        // ---- cell update: thread owns col (c0+col), batches {bt, bt+16} ----
        __nv_bfloat16* hhn = g_hh[(t + 1) & 1];
        __nv_bfloat16* hln = g_hl[(t + 1) & 1];
#pragma unroll
        for (int bi = 0; bi < 2; ++bi) {
            int l = bt + 16 * bi;
            float pi = Drow[l * 68 +  0 + col] + xr[bi][0];
            float pf = Drow[l * 68 + 16 + col] + xr[bi][1];
            float pg = Drow[l * 68 + 32 + col] + xr[bi][2];
            float po = Drow[l * 68 + 48 + col] + xr[bi][3];
            float ig = 1.0f / (1.0f + expf(-pi));
            float fg = 1.0f / (1.0f + expf(-pf));
            float gg = tanhf(pg);
            float og = 1.0f / (1.0f + expf(-po));
            float c  = fg * cst[bi] + ig * gg;
            cst[bi] = c;
            float hv = og * tanhf(c);
            __nv_bfloat16 hi = __float2bfloat16_rn(hv);
            __nv_bfloat16 lo = __float2bfloat16_rn(hv - __bfloat162float(hi));
            size_t idx = (size_t)(b0g + l) * HH + c0 + col;
            hhn[idx] = hi;
            hln[idx] = lo;
        }
#pragma unroll
        for (int bi = 0; bi < 2; ++bi)
#pragma unroll
            for (int g = 0; g < 4; ++g) xr[bi][g] = xn[bi][g];

        // ---- per-group barrier (32 CTAs sharing batch group bg) ----
        __syncthreads();
        if (tid == 0) {
            int* ctr = &g_ctr4[bg << 5];
            asm volatile("red.release.gpu.global.add.s32 [%0], 1;" :: "l"(ctr) : "memory");
            const int target = 32 * (t + 1);
            int v;
            do {
                asm volatile("ld.acquire.gpu.global.s32 %0, [%1];" : "=r"(v) : "l"(ctr) : "memory");
            } while (v < target);
        }
        __syncthreads();
    }
}

// ---------------------------------------------------------------------------
// Phase 3: out[b] = sigmoid(h_last . W_fc + b_fc). t=1023 wrote plane 0.
__global__ void fc_out(const float* __restrict__ W_fc, const float* __restrict__ b_fc,
                       float* __restrict__ out) {
    __shared__ float red[128];
    const int b = blockIdx.x, tid = threadIdx.x;
    const __nv_bfloat16* hh = g_hh[0] + b * HH;
    const __nv_bfloat16* hl = g_hl[0] + b * HH;
    float s = 0.0f;
#pragma unroll
    for (int k = tid; k < HH; k += 128) {
        float hv = __bfloat162float(hh[k]) + __bfloat162float(hl[k]);
        s = fmaf(hv, W_fc[k], s);
    }
    red[tid] = s;
    __syncthreads();
    for (int off = 64; off > 0; off >>= 1) {
        if (tid < off) red[tid] += red[tid + off];
        __syncthreads();
    }
    if (tid == 0) out[b] = 1.0f / (1.0f + expf(-(red[0] + b_fc[0])));
}

// ---------------------------------------------------------------------------
extern "C" void kernel_launch(void* const* d_in, const int* in_sizes, int n_in,
                              void* d_out, int out_size) {
    const float* x    = (const float*)d_in[0];
    const float* W_ih = (const float*)d_in[1];
    const float* W_hh = (const float*)d_in[2];
    const float* b_ih = (const float*)d_in[3];
    const float* b_hh = (const float*)d_in[4];
    const float* W_fc = (const float*)d_in[5];
    const float* b_fc = (const float*)d_in[6];
    float* out = (float*)d_out;

    cudaFuncSetAttribute(xg_hmma,  cudaFuncAttributeMaxDynamicSharedMemorySize, SMEM1_BYTES);
    cudaFuncSetAttribute(lstm_mma, cudaFuncAttributeMaxDynamicSharedMemorySize, SMEM_BYTES);

    init_state<<<256, 256>>>();
    xg_hmma<<<dim3(1024, 16), 256, SMEM1_BYTES>>>(x, W_ih, b_ih, b_hh);
    lstm_mma<<<NCTA, 256, SMEM_BYTES>>>(W_hh);
    fc_out<<<BB, 128>>>(W_fc, b_fc, out);
}

// round 14
// speedup vs baseline: 3.0542x; 1.2095x over previous
#include <cuda_runtime.h>
#include <cuda_bf16.h>
#include <cuda_fp16.h>
#include <cstdint>

#define TT 1024
#define BB 128
#define DD 128
#define HH 512
#define G4 2048   // 4*HH
#define NCTA 128  // persistent grid: 32 col-slices x 4 batch-groups

// ---- phase-2 SMEM layout (rows padded to 1040 B -> conflict-free ldmatrix) ----
#define WF  0                       // [64][520] fp16  W (single plane)
#define HHI 66560                   // [32][520] fp16  h hi
#define HLO 99840                   // [32][520] fp16  h lo
#define DSM 133120                  // [32][68] fp32   D tile
#define SMEM_BYTES 141824

// ---- phase-1 SMEM layout (rows padded to 272 B) ----
#define XHI1 0                      // [128][136] bf16 x hi
#define XLO1 34816                  // [128][136] bf16 x lo
#define WHI1 69632                  // [128][136] bf16 W hi
#define WLO1 104448                 // [128][136] bf16 W lo
#define BIAS1 139264                // [128] f32
#define SMEM1_BYTES 139776
// D overlay [128][132] f32 over XHI1/XLO1 after MMA

// Scratch (allocation-free rule: __device__ globals)
static __device__ float g_xg[(size_t)TT * BB * G4];        // [t][b][4H] (~1GB)
static __device__ __half g_hh[2][BB * HH];                 // h hi plane (ping-pong)
static __device__ __half g_hl[2][BB * HH];                 // h lo plane
static __device__ int g_ctr4[128];                         // 4 group barriers, 128B apart

// ---------------------------------------------------------------------------
__global__ void init_state() {
    int i = blockIdx.x * blockDim.x + threadIdx.x;
    if (i < BB * HH) {
        g_hh[0][i] = __float2half_rn(0.0f); g_hl[0][i] = __float2half_rn(0.0f);
        g_hh[1][i] = __float2half_rn(0.0f); g_hl[1][i] = __float2half_rn(0.0f);
    }
    if (i < 128) g_ctr4[i] = 0;
}

// ---------------------------------------------------------------------------
// mma.sync / ldmatrix helpers (sm_80+ baseline PTX)
// ---------------------------------------------------------------------------
#define LDSM_X4(r0, r1, r2, r3, a) \
    asm volatile("ldmatrix.sync.aligned.m8n8.x4.shared.b16 {%0,%1,%2,%3}, [%4];" \
                 : "=r"(r0), "=r"(r1), "=r"(r2), "=r"(r3) : "r"(a))
#define LDSM_X2(r0, r1, a) \
    asm volatile("ldmatrix.sync.aligned.m8n8.x2.shared.b16 {%0,%1}, [%2];" \
                 : "=r"(r0), "=r"(r1) : "r"(a))
#define MMA16816BF(c, a0, a1, a2, a3, b0, b1) \
    asm volatile("mma.sync.aligned.m16n8k16.row.col.f32.bf16.bf16.f32 " \
                 "{%0,%1,%2,%3}, {%4,%5,%6,%7}, {%8,%9}, {%0,%1,%2,%3};" \
                 : "+f"((c)[0]), "+f"((c)[1]), "+f"((c)[2]), "+f"((c)[3]) \
                 : "r"(a0), "r"(a1), "r"(a2), "r"(a3), "r"(b0), "r"(b1))
#define MMA16816F16(c, a0, a1, a2, a3, b0, b1) \
    asm volatile("mma.sync.aligned.m16n8k16.row.col.f32.f16.f16.f32 " \
                 "{%0,%1,%2,%3}, {%4,%5,%6,%7}, {%8,%9}, {%0,%1,%2,%3};" \
                 : "+f"((c)[0]), "+f"((c)[1]), "+f"((c)[2]), "+f"((c)[3]) \
                 : "r"(a0), "r"(a1), "r"(a2), "r"(a3), "r"(b0), "r"(b1))

__device__ __forceinline__ void cp16(uint32_t dst, const void* src) {
    asm volatile("cp.async.cg.shared.global [%0], [%1], 16;\n" :: "r"(dst), "l"(src));
}
__device__ __forceinline__ void cp_commit() { asm volatile("cp.async.commit_group;\n"); }
__device__ __forceinline__ void cp_wait0()  { asm volatile("cp.async.wait_group 0;\n"); }

// bf16 packers (phase 1)
__device__ __forceinline__ uint32_t pk_hi(float x, float y, float& rx, float& ry) {
    __nv_bfloat16 hx = __float2bfloat16_rn(x), hy = __float2bfloat16_rn(y);
    rx = x - __bfloat162float(hx);
    ry = y - __bfloat162float(hy);
    return ((uint32_t)__bfloat16_as_ushort(hy) << 16) | __bfloat16_as_ushort(hx);
}
__device__ __forceinline__ uint32_t pk(float x, float y) {
    __nv_bfloat16 hx = __float2bfloat16_rn(x), hy = __float2bfloat16_rn(y);
    return ((uint32_t)__bfloat16_as_ushort(hy) << 16) | __bfloat16_as_ushort(hx);
}
// fp16 packer (phase 2 W)
__device__ __forceinline__ uint32_t pkh(float x, float y) {
    __half hx = __float2half_rn(x), hy = __float2half_rn(y);
    return ((uint32_t)__half_as_ushort(hy) << 16) | __half_as_ushort(hx);
}

__device__ __forceinline__ float fsigmoid(float x) {
    return __fdividef(1.0f, 1.0f + __expf(-x));
}
__device__ __forceinline__ float ftanh(float x) {
    return __fdividef(2.0f, 1.0f + __expf(-2.0f * x)) - 1.0f;
}

// ---------------------------------------------------------------------------
// Phase 1 (HMMA): xg[t][b][n] = sum_d x[b,t,d]*W_ih[n,d] + b_ih[n] + b_hh[n]
// CTA tile: M=128 x-rows, N=128 gates, K=128. 3-term bf16 split.
__global__ void __launch_bounds__(256, 1)
xg_hmma(const float* __restrict__ x, const float* __restrict__ W_ih,
        const float* __restrict__ b_ih, const float* __restrict__ b_hh) {
    extern __shared__ char smc[];
    const uint32_t sb = (uint32_t)__cvta_generic_to_shared(smc);
    const int tid = threadIdx.x, wid = tid >> 5, lane = tid & 31;
    const int r0 = blockIdx.x * 128, n0 = blockIdx.y * 128;

#pragma unroll
    for (int i = 0; i < 16; ++i) {
        int o = tid + 256 * i;
        int row = o >> 5, q = o & 31;
        float4 vx = *(const float4*)(x + (size_t)(r0 + row) * DD + q * 4);
        float4 vw = *(const float4*)(W_ih + (size_t)(n0 + row) * DD + q * 4);
        float rx, ry, rz, rw;
        uint32_t xh01 = pk_hi(vx.x, vx.y, rx, ry);
        uint32_t xh23 = pk_hi(vx.z, vx.w, rz, rw);
        *(uint32_t*)(smc + XHI1 + row * 272 + q * 8)     = xh01;
        *(uint32_t*)(smc + XHI1 + row * 272 + q * 8 + 4) = xh23;
        *(uint32_t*)(smc + XLO1 + row * 272 + q * 8)     = pk(rx, ry);
        *(uint32_t*)(smc + XLO1 + row * 272 + q * 8 + 4) = pk(rz, rw);
        uint32_t wh01 = pk_hi(vw.x, vw.y, rx, ry);
        uint32_t wh23 = pk_hi(vw.z, vw.w, rz, rw);
        *(uint32_t*)(smc + WHI1 + row * 272 + q * 8)     = wh01;
        *(uint32_t*)(smc + WHI1 + row * 272 + q * 8 + 4) = wh23;
        *(uint32_t*)(smc + WLO1 + row * 272 + q * 8)     = pk(rx, ry);
        *(uint32_t*)(smc + WLO1 + row * 272 + q * 8 + 4) = pk(rz, rw);
    }
    if (tid < 128) *(float*)(smc + BIAS1 + tid * 4) = b_ih[n0 + tid] + b_hh[n0 + tid];
    __syncthreads();

    const int wm = wid & 1, wn = wid >> 1;
    float acc[4][4][4];
#pragma unroll
    for (int a = 0; a < 4; ++a)
#pragma unroll
        for (int b = 0; b < 4; ++b)
#pragma unroll
            for (int c = 0; c < 4; ++c) acc[a][b][c] = 0.0f;

    uint32_t aA = sb + XHI1 + (uint32_t)((wm * 64 + (lane & 15)) * 272) + ((lane & 16) ? 16u : 0u);
    uint32_t aB = sb + WHI1 + (uint32_t)((wn * 32 + (lane & 7)) * 272) + ((lane & 8) ? 16u : 0u);

#pragma unroll 2
    for (int k = 0; k < 8; ++k) {
        uint32_t ah[4][4], al[4][4], bh[4][2], bl[4][2];
#pragma unroll
        for (int mj = 0; mj < 4; ++mj) {
            LDSM_X4(ah[mj][0], ah[mj][1], ah[mj][2], ah[mj][3], aA + mj * 4352u);
            LDSM_X4(al[mj][0], al[mj][1], al[mj][2], al[mj][3], aA + mj * 4352u + 34816u);
        }
#pragma unroll
        for (int nj = 0; nj < 4; ++nj) {
            LDSM_X2(bh[nj][0], bh[nj][1], aB + nj * 2176u);
            LDSM_X2(bl[nj][0], bl[nj][1], aB + nj * 2176u + 34816u);
        }
#pragma unroll
        for (int mj = 0; mj < 4; ++mj)
#pragma unroll
            for (int nj = 0; nj < 4; ++nj) {
                MMA16816BF(acc[mj][nj], ah[mj][0], ah[mj][1], ah[mj][2], ah[mj][3], bh[nj][0], bh[nj][1]);
                MMA16816BF(acc[mj][nj], al[mj][0], al[mj][1], al[mj][2], al[mj][3], bh[nj][0], bh[nj][1]);
                MMA16816BF(acc[mj][nj], ah[mj][0], ah[mj][1], ah[mj][2], ah[mj][3], bl[nj][0], bl[nj][1]);
            }
        aA += 32; aB += 32;
    }
    __syncthreads();

    float* Dsm = (float*)smc;
    {
        int rr = wm * 64 + (lane >> 2), cb = wn * 32 + (lane & 3) * 2;
#pragma unroll
        for (int mj = 0; mj < 4; ++mj)
#pragma unroll
            for (int nj = 0; nj < 4; ++nj) {
                *(float2*)&Dsm[(rr + mj * 16) * 132 + cb + nj * 8]     = make_float2(acc[mj][nj][0], acc[mj][nj][1]);
                *(float2*)&Dsm[(rr + mj * 16 + 8) * 132 + cb + nj * 8] = make_float2(acc[mj][nj][2], acc[mj][nj][3]);
            }
    }
    __syncthreads();

    const float* bias = (const float*)(smc + BIAS1);
#pragma unroll
    for (int i = 0; i < 16; ++i) {
        int o = tid + 256 * i;
        int row = o >> 5, q = o & 31;
        float4 v;
        v.x = Dsm[row * 132 + q * 4]     + bias[q * 4];
        v.y = Dsm[row * 132 + q * 4 + 1] + bias[q * 4 + 1];
        v.z = Dsm[row * 132 + q * 4 + 2] + bias[q * 4 + 2];
        v.w = Dsm[row * 132 + q * 4 + 3] + bias[q * 4 + 3];
        int r = r0 + row;
        int b = r >> 10, tt = r & 1023;
        *(float4*)(g_xg + ((size_t)tt * BB + b) * G4 + n0 + q * 4) = v;
    }
}

// ---------------------------------------------------------------------------
// Phase 2: persistent HMMA LSTM, fp16 2-term split.
// CTA bx: hs=bx&31 -> h-cols [16hs,+16); bg=bx>>5 -> batches [32bg,+32).
// h = hi+lo fp16 planes (~22-bit), W = single fp16 plane (2^-12).
// D[32,64] = (Ahi + Alo) . W^T. Warps 0-3 compute (warp = m16 x n32).
__global__ void __launch_bounds__(256, 1)
lstm_mma(const float* __restrict__ W_hh) {
    extern __shared__ char smc[];
    const uint32_t sb = (uint32_t)__cvta_generic_to_shared(smc);
    const int tid = threadIdx.x, wid = tid >> 5, lane = tid & 31;
    const int hs = blockIdx.x & 31, bg = blockIdx.x >> 5;
    const int c0 = hs * 16, b0g = bg * 32;

    // ---- one-time W slice load -> fp16 (row n = gate(n>>4), col(n&15)) ----
    for (int p = tid; p < 64 * 256; p += 256) {
        int n = p >> 8, kw = p & 255, k = kw * 2;
        int grow = (n >> 4) * HH + c0 + (n & 15);
        float w0 = W_hh[(size_t)grow * HH + k];
        float w1 = W_hh[(size_t)grow * HH + k + 1];
        *(uint32_t*)(smc + WF + n * 1040 + kw * 4) = pkh(w0, w1);
    }
    __syncthreads();

    const int col = tid & 15, bt = tid >> 4;   // epilogue ownership
    float* Drow = (float*)(smc + DSM);
    float cst[2] = {0.0f, 0.0f};

    // initial xg prefetch (t = 0)
    float xr[2][4], xn[2][4];
    {
        const float* xgp = g_xg + (size_t)b0g * G4;
#pragma unroll
        for (int bi = 0; bi < 2; ++bi) {
            int l = bt + 16 * bi;
#pragma unroll
            for (int g = 0; g < 4; ++g)
                xr[bi][g] = __ldcg(xgp + (size_t)l * G4 + g * HH + c0 + col);
        }
    }

    for (int t = 0; t < TT; ++t) {
        // ---- stage h(t) fp16 hi/lo via cp.async ----
        const __half* hhp = g_hh[t & 1];
        const __half* hlp = g_hl[t & 1];
#pragma unroll
        for (int i = 0; i < 16; ++i) {
            int c = tid + 256 * i;              // [0,4096) 16B chunks
            int pl = c >> 11, b = (c >> 6) & 31, kc = c & 63;
            const __half* src = (pl ? hlp : hhp) + (size_t)(b0g + b) * HH + kc * 8;
            uint32_t dst = sb + (pl ? HLO : HHI) + (uint32_t)(b * 1040 + kc * 16);
            cp16(dst, src);
        }
        cp_commit();

        // ---- prefetch xg(t+1) while cp.async runs ----
        {
            int tn = (t + 1 < TT) ? t + 1 : t;
            const float* xgp = g_xg + ((size_t)tn * BB + b0g) * G4;
#pragma unroll
            for (int bi = 0; bi < 2; ++bi) {
                int l = bt + 16 * bi;
#pragma unroll
                for (int g = 0; g < 4; ++g)
                    xn[bi][g] = __ldcg(xgp + (size_t)l * G4 + g * HH + c0 + col);
            }
        }

        cp_wait0();
        __syncthreads();

        // ---- tensor-core loop: 4 compute warps, warp = m16(wm) x n32(wn) ----
        if (wid < 4) {
            const int wm = wid & 1, wn = wid >> 1;
            float acc[4][4];
#pragma unroll
            for (int a = 0; a < 4; ++a)
#pragma unroll
                for (int b = 0; b < 4; ++b) acc[a][b] = 0.0f;

            uint32_t aA = sb + HHI + (uint32_t)((wm * 16 + (lane & 15)) * 1040) + ((lane & 16) ? 16u : 0u);
            uint32_t aB = sb + WF + (uint32_t)((wn * 32 + (lane & 7)) * 1040) + (uint32_t)((lane >> 3) * 16);

#pragma unroll 4
            for (int k = 0; k < 16; ++k) {     // k32 blocks
                uint32_t ahA[4], ahB[4], alA[4], alB[4];
                LDSM_X4(ahA[0], ahA[1], ahA[2], ahA[3], aA);
                LDSM_X4(ahB[0], ahB[1], ahB[2], ahB[3], aA + 32u);
                LDSM_X4(alA[0], alA[1], alA[2], alA[3], aA + 33280u);
                LDSM_X4(alB[0], alB[1], alB[2], alB[3], aA + 33280u + 32u);
#pragma unroll
                for (int nj = 0; nj < 4; ++nj) {
                    uint32_t bh[4];
                    LDSM_X4(bh[0], bh[1], bh[2], bh[3], aB + nj * 8320u);
                    MMA16816F16(acc[nj], ahA[0], ahA[1], ahA[2], ahA[3], bh[0], bh[1]);
                    MMA16816F16(acc[nj], alA[0], alA[1], alA[2], alA[3], bh[0], bh[1]);
                    MMA16816F16(acc[nj], ahB[0], ahB[1], ahB[2], ahB[3], bh[2], bh[3]);
                    MMA16816F16(acc[nj], alB[0], alB[1], alB[2], alB[3], bh[2], bh[3]);
                }
                aA += 64; aB += 64;
            }
            int rr = wm * 16 + (lane >> 2), cb = wn * 32 + (lane & 3) * 2;
#pragma unroll
            for (int nj = 0; nj < 4; ++nj) {
                *(float2*)&Drow[rr * 68 + cb + nj * 8]       = make_float2(acc[nj][0], acc[nj][1]);
                *(float2*)&Drow[(rr + 8) * 68 + cb + nj * 8] = make_float2(acc[nj][2], acc[nj][3]);
            }
        }
        __syncthreads();

        // ---- cell update: thread owns col (c0+col), batches {bt, bt+16} ----
        __half* hhn = g_hh[(t + 1) & 1];
        __half* hln = g_hl[(t + 1) & 1];
#pragma unroll
        for (int bi = 0; bi < 2; ++bi) {
            int l = bt + 16 * bi;
            float pi = Drow[l * 68 +  0 + col] + xr[bi][0];
            float pf = Drow[l * 68 + 16 + col] + xr[bi][1];
            float pg = Drow[l * 68 + 32 + col] + xr[bi][2];
            float po = Drow[l * 68 + 48 + col] + xr[bi][3];
            float ig = fsigmoid(pi);
            float fg = fsigmoid(pf);
            float gg = ftanh(pg);
            float og = fsigmoid(po);
            float c  = fg * cst[bi] + ig * gg;
            cst[bi] = c;
            float hv = og * ftanh(c);
            __half hi = __float2half_rn(hv);
            __half lo = __float2half_rn(hv - __half2float(hi));
            size_t idx = (size_t)(b0g + l) * HH + c0 + col;
            hhn[idx] = hi;
            hln[idx] = lo;
        }
#pragma unroll
        for (int bi = 0; bi < 2; ++bi)
#pragma unroll
            for (int g = 0; g < 4; ++g) xr[bi][g] = xn[bi][g];

        // ---- per-group barrier (32 CTAs sharing batch group bg) ----
        __syncthreads();
        if (tid == 0) {
            int* ctr = &g_ctr4[bg << 5];
            asm volatile("red.release.gpu.global.add.s32 [%0], 1;" :: "l"(ctr) : "memory");
            const int target = 32 * (t + 1);
            int v;
            do {
                asm volatile("ld.acquire.gpu.global.s32 %0, [%1];" : "=r"(v) : "l"(ctr) : "memory");
            } while (v < target);
        }
        __syncthreads();
    }
}

// ---------------------------------------------------------------------------
// Phase 3: out[b] = sigmoid(h_last . W_fc + b_fc). t=1023 wrote plane 0.
__global__ void fc_out(const float* __restrict__ W_fc, const float* __restrict__ b_fc,
                       float* __restrict__ out) {
    __shared__ float red[128];
    const int b = blockIdx.x, tid = threadIdx.x;
    const __half* hh = g_hh[0] + b * HH;
    const __half* hl = g_hl[0] + b * HH;
    float s = 0.0f;
#pragma unroll
    for (int k = tid; k < HH; k += 128) {
        float hv = __half2float(hh[k]) + __half2float(hl[k]);
        s = fmaf(hv, W_fc[k], s);
    }
    red[tid] = s;
    __syncthreads();
    for (int off = 64; off > 0; off >>= 1) {
        if (tid < off) red[tid] += red[tid + off];
        __syncthreads();
    }
    if (tid == 0) out[b] = 1.0f / (1.0f + expf(-(red[0] + b_fc[0])));
}

// ---------------------------------------------------------------------------
extern "C" void kernel_launch(void* const* d_in, const int* in_sizes, int n_in,
                              void* d_out, int out_size) {
    const float* x    = (const float*)d_in[0];
    const float* W_ih = (const float*)d_in[1];
    const float* W_hh = (const float*)d_in[2];
    const float* b_ih = (const float*)d_in[3];
    const float* b_hh = (const float*)d_in[4];
    const float* W_fc = (const float*)d_in[5];
    const float* b_fc = (const float*)d_in[6];
    float* out = (float*)d_out;

    cudaFuncSetAttribute(xg_hmma,  cudaFuncAttributeMaxDynamicSharedMemorySize, SMEM1_BYTES);
    cudaFuncSetAttribute(lstm_mma, cudaFuncAttributeMaxDynamicSharedMemorySize, SMEM_BYTES);

    init_state<<<256, 256>>>();
    xg_hmma<<<dim3(1024, 16), 256, SMEM1_BYTES>>>(x, W_ih, b_ih, b_hh);
    lstm_mma<<<NCTA, 256, SMEM_BYTES>>>(W_hh);
    fc_out<<<BB, 128>>>(W_fc, b_fc, out);
}

// round 15
// speedup vs baseline: 3.5364x; 1.1579x over previous
#include <cuda_runtime.h>
#include <cuda_bf16.h>
#include <cuda_fp16.h>
#include <cstdint>

#define TT 1024
#define BB 128
#define DD 128
#define HH 512
#define G4 2048   // 4*HH
#define NCTA 128  // persistent grid: 32 col-slices x 4 batch-groups

// ---- phase-2 SMEM layout (rows padded to 1040 B -> conflict-free ldmatrix) ----
#define WF  0                       // [64][520] fp16  W (single plane)
#define HHI 66560                   // [32][520] fp16  h (single plane)
#define DSM 99840                   // [32][68] fp32   D tile
#define SMEM_BYTES 108544

// ---- phase-1 SMEM layout (rows padded to 272 B) ----
#define XHI1 0                      // [128][136] fp16 x hi
#define XLO1 34816                  // [128][136] fp16 x lo
#define WF1  69632                  // [128][136] fp16 W (single plane)
#define BIAS1 104448                // [128] f32
#define SMEM1_BYTES 104960
// D overlay [128][132] f32 = 67584 B over XHI1/XLO1 after MMA

// Scratch (allocation-free rule: __device__ globals)
static __device__ __half g_xg[(size_t)TT * BB * G4];       // [t][b][4H] fp16 (~0.5GB)
static __device__ __half g_hh[2][BB * HH];                 // h plane (ping-pong)
static __device__ int g_ctr4[128];                         // 4 group barriers, 128B apart

// ---------------------------------------------------------------------------
__global__ void init_state() {
    int i = blockIdx.x * blockDim.x + threadIdx.x;
    if (i < BB * HH) {
        g_hh[0][i] = __float2half_rn(0.0f);
        g_hh[1][i] = __float2half_rn(0.0f);
    }
    if (i < 128) g_ctr4[i] = 0;
}

// ---------------------------------------------------------------------------
// mma.sync / ldmatrix helpers (sm_80+ baseline PTX)
// ---------------------------------------------------------------------------
#define LDSM_X4(r0, r1, r2, r3, a) \
    asm volatile("ldmatrix.sync.aligned.m8n8.x4.shared.b16 {%0,%1,%2,%3}, [%4];" \
                 : "=r"(r0), "=r"(r1), "=r"(r2), "=r"(r3) : "r"(a))
#define LDSM_X2(r0, r1, a) \
    asm volatile("ldmatrix.sync.aligned.m8n8.x2.shared.b16 {%0,%1}, [%2];" \
                 : "=r"(r0), "=r"(r1) : "r"(a))
#define MMA16816F16(c, a0, a1, a2, a3, b0, b1) \
    asm volatile("mma.sync.aligned.m16n8k16.row.col.f32.f16.f16.f32 " \
                 "{%0,%1,%2,%3}, {%4,%5,%6,%7}, {%8,%9}, {%0,%1,%2,%3};" \
                 : "+f"((c)[0]), "+f"((c)[1]), "+f"((c)[2]), "+f"((c)[3]) \
                 : "r"(a0), "r"(a1), "r"(a2), "r"(a3), "r"(b0), "r"(b1))

__device__ __forceinline__ void cp16(uint32_t dst, const void* src) {
    asm volatile("cp.async.cg.shared.global [%0], [%1], 16;\n" :: "r"(dst), "l"(src));
}
__device__ __forceinline__ void cp_commit() { asm volatile("cp.async.commit_group;\n"); }
__device__ __forceinline__ void cp_wait0()  { asm volatile("cp.async.wait_group 0;\n"); }

// fp16 packers
__device__ __forceinline__ uint32_t pkh(float x, float y) {
    __half hx = __float2half_rn(x), hy = __float2half_rn(y);
    return ((uint32_t)__half_as_ushort(hy) << 16) | __half_as_ushort(hx);
}
__device__ __forceinline__ uint32_t pkh_hi(float x, float y, float& rx, float& ry) {
    __half hx = __float2half_rn(x), hy = __float2half_rn(y);
    rx = x - __half2float(hx);
    ry = y - __half2float(hy);
    return ((uint32_t)__half_as_ushort(hy) << 16) | __half_as_ushort(hx);
}

__device__ __forceinline__ float fsigmoid(float x) {
    return __fdividef(1.0f, 1.0f + __expf(-x));
}
__device__ __forceinline__ float ftanh(float x) {
    return __fdividef(2.0f, 1.0f + __expf(-2.0f * x)) - 1.0f;
}

// ---------------------------------------------------------------------------
// Phase 1 (HMMA): xg[t][b][n] = sum_d x[b,t,d]*W_ih[n,d] + b_ih[n] + b_hh[n]
// CTA tile: M=128 x-rows, N=128 gates, K=128. fp16 2-term (x hi/lo, W single).
__global__ void __launch_bounds__(256, 1)
xg_hmma(const float* __restrict__ x, const float* __restrict__ W_ih,
        const float* __restrict__ b_ih, const float* __restrict__ b_hh) {
    extern __shared__ char smc[];
    const uint32_t sb = (uint32_t)__cvta_generic_to_shared(smc);
    const int tid = threadIdx.x, wid = tid >> 5, lane = tid & 31;
    const int r0 = blockIdx.x * 128, n0 = blockIdx.y * 128;

#pragma unroll
    for (int i = 0; i < 16; ++i) {
        int o = tid + 256 * i;
        int row = o >> 5, q = o & 31;
        float4 vx = *(const float4*)(x + (size_t)(r0 + row) * DD + q * 4);
        float4 vw = *(const float4*)(W_ih + (size_t)(n0 + row) * DD + q * 4);
        float rx, ry, rz, rw;
        uint32_t xh01 = pkh_hi(vx.x, vx.y, rx, ry);
        uint32_t xh23 = pkh_hi(vx.z, vx.w, rz, rw);
        *(uint32_t*)(smc + XHI1 + row * 272 + q * 8)     = xh01;
        *(uint32_t*)(smc + XHI1 + row * 272 + q * 8 + 4) = xh23;
        *(uint32_t*)(smc + XLO1 + row * 272 + q * 8)     = pkh(rx, ry);
        *(uint32_t*)(smc + XLO1 + row * 272 + q * 8 + 4) = pkh(rz, rw);
        *(uint32_t*)(smc + WF1 + row * 272 + q * 8)      = pkh(vw.x, vw.y);
        *(uint32_t*)(smc + WF1 + row * 272 + q * 8 + 4)  = pkh(vw.z, vw.w);
    }
    if (tid < 128) *(float*)(smc + BIAS1 + tid * 4) = b_ih[n0 + tid] + b_hh[n0 + tid];
    __syncthreads();

    const int wm = wid & 1, wn = wid >> 1;
    float acc[4][4][4];
#pragma unroll
    for (int a = 0; a < 4; ++a)
#pragma unroll
        for (int b = 0; b < 4; ++b)
#pragma unroll
            for (int c = 0; c < 4; ++c) acc[a][b][c] = 0.0f;

    uint32_t aA = sb + XHI1 + (uint32_t)((wm * 64 + (lane & 15)) * 272) + ((lane & 16) ? 16u : 0u);
    uint32_t aB = sb + WF1 + (uint32_t)((wn * 32 + (lane & 7)) * 272) + ((lane & 8) ? 16u : 0u);

#pragma unroll 2
    for (int k = 0; k < 8; ++k) {
        uint32_t ah[4][4], al[4][4], bh[4][2];
#pragma unroll
        for (int mj = 0; mj < 4; ++mj) {
            LDSM_X4(ah[mj][0], ah[mj][1], ah[mj][2], ah[mj][3], aA + mj * 4352u);
            LDSM_X4(al[mj][0], al[mj][1], al[mj][2], al[mj][3], aA + mj * 4352u + 34816u);
        }
#pragma unroll
        for (int nj = 0; nj < 4; ++nj)
            LDSM_X2(bh[nj][0], bh[nj][1], aB + nj * 2176u);
#pragma unroll
        for (int mj = 0; mj < 4; ++mj)
#pragma unroll
            for (int nj = 0; nj < 4; ++nj) {
                MMA16816F16(acc[mj][nj], ah[mj][0], ah[mj][1], ah[mj][2], ah[mj][3], bh[nj][0], bh[nj][1]);
                MMA16816F16(acc[mj][nj], al[mj][0], al[mj][1], al[mj][2], al[mj][3], bh[nj][0], bh[nj][1]);
            }
        aA += 32; aB += 32;
    }
    __syncthreads();   // x reads done; D overlays x region

    float* Dsm = (float*)smc;
    {
        int rr = wm * 64 + (lane >> 2), cb = wn * 32 + (lane & 3) * 2;
#pragma unroll
        for (int mj = 0; mj < 4; ++mj)
#pragma unroll
            for (int nj = 0; nj < 4; ++nj) {
                *(float2*)&Dsm[(rr + mj * 16) * 132 + cb + nj * 8]     = make_float2(acc[mj][nj][0], acc[mj][nj][1]);
                *(float2*)&Dsm[(rr + mj * 16 + 8) * 132 + cb + nj * 8] = make_float2(acc[mj][nj][2], acc[mj][nj][3]);
            }
    }
    __syncthreads();

    const float* bias = (const float*)(smc + BIAS1);
#pragma unroll
    for (int i = 0; i < 16; ++i) {
        int o = tid + 256 * i;
        int row = o >> 5, q = o & 31;
        float vx = Dsm[row * 132 + q * 4]     + bias[q * 4];
        float vy = Dsm[row * 132 + q * 4 + 1] + bias[q * 4 + 1];
        float vz = Dsm[row * 132 + q * 4 + 2] + bias[q * 4 + 2];
        float vw = Dsm[row * 132 + q * 4 + 3] + bias[q * 4 + 3];
        int r = r0 + row;
        int b = r >> 10, tt = r & 1023;
        uint2 pack = make_uint2(pkh(vx, vy), pkh(vz, vw));
        *(uint2*)(g_xg + ((size_t)tt * BB + b) * G4 + n0 + q * 4) = pack;
    }
}

// ---------------------------------------------------------------------------
// Phase 2: persistent HMMA LSTM, all-fp16 single-plane operands.
// CTA bx: hs=bx&31 -> h-cols [16hs,+16); bg=bx>>5 -> batches [32bg,+32).
// D[32,64] = h . W^T, 1 MMA term. Warps 0-3 compute (warp = m16 x n32).
__global__ void __launch_bounds__(256, 1)
lstm_mma(const float* __restrict__ W_hh) {
    extern __shared__ char smc[];
    const uint32_t sb = (uint32_t)__cvta_generic_to_shared(smc);
    const int tid = threadIdx.x, wid = tid >> 5, lane = tid & 31;
    const int hs = blockIdx.x & 31, bg = blockIdx.x >> 5;
    const int c0 = hs * 16, b0g = bg * 32;

    // ---- one-time W slice load -> fp16 (row n = gate(n>>4), col(n&15)) ----
    for (int p = tid; p < 64 * 256; p += 256) {
        int n = p >> 8, kw = p & 255, k = kw * 2;
        int grow = (n >> 4) * HH + c0 + (n & 15);
        float w0 = W_hh[(size_t)grow * HH + k];
        float w1 = W_hh[(size_t)grow * HH + k + 1];
        *(uint32_t*)(smc + WF + n * 1040 + kw * 4) = pkh(w0, w1);
    }
    __syncthreads();

    const int col = tid & 15, bt = tid >> 4;   // epilogue ownership
    float* Drow = (float*)(smc + DSM);
    float cst[2] = {0.0f, 0.0f};

    // initial xg prefetch (t = 0)
    float xr[2][4], xn[2][4];
    {
        const __half* xgp = g_xg + (size_t)b0g * G4;
#pragma unroll
        for (int bi = 0; bi < 2; ++bi) {
            int l = bt + 16 * bi;
#pragma unroll
            for (int g = 0; g < 4; ++g)
                xr[bi][g] = __half2float(__ldcg(xgp + (size_t)l * G4 + g * HH + c0 + col));
        }
    }

    for (int t = 0; t < TT; ++t) {
        // ---- stage h(t) fp16 via cp.async (32 KB) ----
        const __half* hhp = g_hh[t & 1];
#pragma unroll
        for (int i = 0; i < 8; ++i) {
            int c = tid + 256 * i;              // [0,2048) 16B chunks
            int b = c >> 6, kc = c & 63;
            cp16(sb + HHI + (uint32_t)(b * 1040 + kc * 16),
                 hhp + (size_t)(b0g + b) * HH + kc * 8);
        }
        cp_commit();

        // ---- prefetch xg(t+1) while cp.async runs ----
        {
            int tn = (t + 1 < TT) ? t + 1 : t;
            const __half* xgp = g_xg + ((size_t)tn * BB + b0g) * G4;
#pragma unroll
            for (int bi = 0; bi < 2; ++bi) {
                int l = bt + 16 * bi;
#pragma unroll
                for (int g = 0; g < 4; ++g)
                    xn[bi][g] = __half2float(__ldcg(xgp + (size_t)l * G4 + g * HH + c0 + col));
            }
        }

        cp_wait0();
        __syncthreads();

        // ---- tensor-core loop: 4 compute warps, warp = m16(wm) x n32(wn) ----
        if (wid < 4) {
            const int wm = wid & 1, wn = wid >> 1;
            float acc[4][4];
#pragma unroll
            for (int a = 0; a < 4; ++a)
#pragma unroll
                for (int b = 0; b < 4; ++b) acc[a][b] = 0.0f;

            uint32_t aA = sb + HHI + (uint32_t)((wm * 16 + (lane & 15)) * 1040) + ((lane & 16) ? 16u : 0u);
            uint32_t aB = sb + WF + (uint32_t)((wn * 32 + (lane & 7)) * 1040) + (uint32_t)((lane >> 3) * 16);

#pragma unroll 4
            for (int k = 0; k < 16; ++k) {     // k32 blocks
                uint32_t ahA[4], ahB[4];
                LDSM_X4(ahA[0], ahA[1], ahA[2], ahA[3], aA);
                LDSM_X4(ahB[0], ahB[1], ahB[2], ahB[3], aA + 32u);
#pragma unroll
                for (int nj = 0; nj < 4; ++nj) {
                    uint32_t bh[4];
                    LDSM_X4(bh[0], bh[1], bh[2], bh[3], aB + nj * 8320u);
                    MMA16816F16(acc[nj], ahA[0], ahA[1], ahA[2], ahA[3], bh[0], bh[1]);
                    MMA16816F16(acc[nj], ahB[0], ahB[1], ahB[2], ahB[3], bh[2], bh[3]);
                }
                aA += 64; aB += 64;
            }
            int rr = wm * 16 + (lane >> 2), cb = wn * 32 + (lane & 3) * 2;
#pragma unroll
            for (int nj = 0; nj < 4; ++nj) {
                *(float2*)&Drow[rr * 68 + cb + nj * 8]       = make_float2(acc[nj][0], acc[nj][1]);
                *(float2*)&Drow[(rr + 8) * 68 + cb + nj * 8] = make_float2(acc[nj][2], acc[nj][3]);
            }
        }
        __syncthreads();

        // ---- cell update: thread owns col (c0+col), batches {bt, bt+16} ----
        __half* hhn = g_hh[(t + 1) & 1];
#pragma unroll
        for (int bi = 0; bi < 2; ++bi) {
            int l = bt + 16 * bi;
            float pi = Drow[l * 68 +  0 + col] + xr[bi][0];
            float pf = Drow[l * 68 + 16 + col] + xr[bi][1];
            float pg = Drow[l * 68 + 32 + col] + xr[bi][2];
            float po = Drow[l * 68 + 48 + col] + xr[bi][3];
            float ig = fsigmoid(pi);
            float fg = fsigmoid(pf);
            float gg = ftanh(pg);
            float og = fsigmoid(po);
            float c  = fg * cst[bi] + ig * gg;
            cst[bi] = c;
            float hv = og * ftanh(c);
            hhn[(size_t)(b0g + l) * HH + c0 + col] = __float2half_rn(hv);
        }
#pragma unroll
        for (int bi = 0; bi < 2; ++bi)
#pragma unroll
            for (int g = 0; g < 4; ++g) xr[bi][g] = xn[bi][g];

        // ---- per-group barrier (32 CTAs sharing batch group bg) ----
        __syncthreads();
        if (tid == 0) {
            int* ctr = &g_ctr4[bg << 5];
            asm volatile("red.release.gpu.global.add.s32 [%0], 1;" :: "l"(ctr) : "memory");
            const int target = 32 * (t + 1);
            int v;
            do {
                asm volatile("ld.acquire.gpu.global.s32 %0, [%1];" : "=r"(v) : "l"(ctr) : "memory");
            } while (v < target);
        }
        __syncthreads();
    }
}

// ---------------------------------------------------------------------------
// Phase 3: out[b] = sigmoid(h_last . W_fc + b_fc). t=1023 wrote plane 0.
__global__ void fc_out(const float* __restrict__ W_fc, const float* __restrict__ b_fc,
                       float* __restrict__ out) {
    __shared__ float red[128];
    const int b = blockIdx.x, tid = threadIdx.x;
    const __half* hh = g_hh[0] + b * HH;
    float s = 0.0f;
#pragma unroll
    for (int k = tid; k < HH; k += 128)
        s = fmaf(__half2float(hh[k]), W_fc[k], s);
    red[tid] = s;
    __syncthreads();
    for (int off = 64; off > 0; off >>= 1) {
        if (tid < off) red[tid] += red[tid + off];
        __syncthreads();
    }
    if (tid == 0) out[b] = 1.0f / (1.0f + expf(-(red[0] + b_fc[0])));
}

// ---------------------------------------------------------------------------
extern "C" void kernel_launch(void* const* d_in, const int* in_sizes, int n_in,
                              void* d_out, int out_size) {
    const float* x    = (const float*)d_in[0];
    const float* W_ih = (const float*)d_in[1];
    const float* W_hh = (const float*)d_in[2];
    const float* b_ih = (const float*)d_in[3];
    const float* b_hh = (const float*)d_in[4];
    const float* W_fc = (const float*)d_in[5];
    const float* b_fc = (const float*)d_in[6];
    float* out = (float*)d_out;

    cudaFuncSetAttribute(xg_hmma,  cudaFuncAttributeMaxDynamicSharedMemorySize, SMEM1_BYTES);
    cudaFuncSetAttribute(lstm_mma, cudaFuncAttributeMaxDynamicSharedMemorySize, SMEM_BYTES);

    init_state<<<256, 256>>>();
    xg_hmma<<<dim3(1024, 16), 256, SMEM1_BYTES>>>(x, W_ih, b_ih, b_hh);
    lstm_mma<<<NCTA, 256, SMEM_BYTES>>>(W_hh);
    fc_out<<<BB, 128>>>(W_fc, b_fc, out);
}

// round 17
// speedup vs baseline: 4.1175x; 1.1643x over previous
#include <cuda_runtime.h>
#include <cuda_bf16.h>
#include <cuda_fp16.h>
#include <cstdint>

#define TT 1024
#define BB 128
#define DD 128
#define HH 512
#define G4 2048   // 4*HH
#define NCTA 128  // persistent grid: 32 col-slices x 4 batch-groups

// ---- phase-2 SMEM layout (rows padded to 1040 B -> conflict-free ldmatrix) ----
#define WF  0                       // [64][520] fp16  W (single plane)
#define HHI 66560                   // [32][520] fp16  h (single plane)
#define DSM 99840                   // [32][68] fp32   D tile
#define SMEM_BYTES 108544

// ---- phase-1 SMEM layout (rows padded to 272 B) ----
#define XS1 0                       // [128][136] fp16 x tile
#define WS1 34816                   // [128][136] fp16 W tile
#define BIAS1 69632                 // [128] f32
#define SMEM1_BYTES 70144
// D overlay [128][132] f32 = 67584 B over XS1/WS1 after MMA

// Scratch (allocation-free rule: __device__ globals)
static __device__ __half g_xg[(size_t)TT * BB * G4];       // [t][b][4H] fp16 (~0.5GB)
static __device__ __half g_xh[(size_t)BB * TT * DD];       // x pre-converted fp16 (32MB)
static __device__ __half g_wih[(size_t)G4 * DD];           // W_ih fp16 (0.5MB)
static __device__ __half g_hh[2][BB * HH];                 // h plane (ping-pong)
static __device__ int g_ctr4[128];                         // 4 group barriers, 128B apart

// ---------------------------------------------------------------------------
__global__ void init_state() {
    int i = blockIdx.x * blockDim.x + threadIdx.x;
    if (i < BB * HH) {
        g_hh[0][i] = __float2half_rn(0.0f);
        g_hh[1][i] = __float2half_rn(0.0f);
    }
    if (i < 128) g_ctr4[i] = 0;
}

// fp16 packers
__device__ __forceinline__ uint32_t pkh(float x, float y) {
    __half hx = __float2half_rn(x), hy = __float2half_rn(y);
    return ((uint32_t)__half_as_ushort(hy) << 16) | __half_as_ushort(hx);
}

// Phase 0: one-time fp32 -> fp16 conversion of x and W_ih.
#define XF4 ((BB * TT * DD) / 4)    // 4194304 float4-groups
#define WF4 ((G4 * DD) / 4)         // 65536
__global__ void cvt_in(const float* __restrict__ x, const float* __restrict__ W_ih) {
    int i = blockIdx.x * blockDim.x + threadIdx.x;
    if (i < XF4) {
        float4 v = *(const float4*)(x + (size_t)i * 4);
        *(uint2*)(g_xh + (size_t)i * 4) = make_uint2(pkh(v.x, v.y), pkh(v.z, v.w));
    } else if (i < XF4 + WF4) {
        int j = i - XF4;
        float4 v = *(const float4*)(W_ih + (size_t)j * 4);
        *(uint2*)(g_wih + (size_t)j * 4) = make_uint2(pkh(v.x, v.y), pkh(v.z, v.w));
    }
}

// ---------------------------------------------------------------------------
// mma.sync / ldmatrix helpers (sm_80+ baseline PTX)
// ---------------------------------------------------------------------------
#define LDSM_X4(r0, r1, r2, r3, a) \
    asm volatile("ldmatrix.sync.aligned.m8n8.x4.shared.b16 {%0,%1,%2,%3}, [%4];" \
                 : "=r"(r0), "=r"(r1), "=r"(r2), "=r"(r3) : "r"(a))
#define LDSM_X2(r0, r1, a) \
    asm volatile("ldmatrix.sync.aligned.m8n8.x2.shared.b16 {%0,%1}, [%2];" \
                 : "=r"(r0), "=r"(r1) : "r"(a))
#define MMA16816F16(c, a0, a1, a2, a3, b0, b1) \
    asm volatile("mma.sync.aligned.m16n8k16.row.col.f32.f16.f16.f32 " \
                 "{%0,%1,%2,%3}, {%4,%5,%6,%7}, {%8,%9}, {%0,%1,%2,%3};" \
                 : "+f"((c)[0]), "+f"((c)[1]), "+f"((c)[2]), "+f"((c)[3]) \
                 : "r"(a0), "r"(a1), "r"(a2), "r"(a3), "r"(b0), "r"(b1))

__device__ __forceinline__ void cp16(uint32_t dst, const void* src) {
    asm volatile("cp.async.cg.shared.global [%0], [%1], 16;\n" :: "r"(dst), "l"(src));
}
__device__ __forceinline__ void cp_commit() { asm volatile("cp.async.commit_group;\n"); }
__device__ __forceinline__ void cp_wait0()  { asm volatile("cp.async.wait_group 0;\n"); }

__device__ __forceinline__ float fsigmoid(float x) {
    return __fdividef(1.0f, 1.0f + __expf(-x));
}
__device__ __forceinline__ float ftanh(float x) {
    return __fdividef(2.0f, 1.0f + __expf(-2.0f * x)) - 1.0f;
}

// ---------------------------------------------------------------------------
// Phase 1 (HMMA): xg[t][b][n] = sum_d x[b,t,d]*W_ih[n,d] + b_ih[n] + b_hh[n]
// CTA tile: M=128 x-rows, N=128 gates, K=128. Single-plane fp16, cp.async staged.
__global__ void __launch_bounds__(256, 1)
xg_hmma(const float* __restrict__ b_ih, const float* __restrict__ b_hh) {
    extern __shared__ char smc[];
    const uint32_t sb = (uint32_t)__cvta_generic_to_shared(smc);
    const int tid = threadIdx.x, wid = tid >> 5, lane = tid & 31;
    const int r0 = blockIdx.x * 128, n0 = blockIdx.y * 128;

    // ---- stage x and W tiles via cp.async (fp16, no conversion) ----
    // per tile: 128 rows x 16 chunks (16B) = 2048 chunks; row = o>>4, kc = o&15
#pragma unroll
    for (int i = 0; i < 8; ++i) {
        int o = tid + 256 * i;              // [0,2048)
        int row = o >> 4, kc = o & 15;
        cp16(sb + XS1 + (uint32_t)(row * 272 + kc * 16),
             g_xh + (size_t)(r0 + row) * DD + kc * 8);
        cp16(sb + WS1 + (uint32_t)(row * 272 + kc * 16),
             g_wih + (size_t)(n0 + row) * DD + kc * 8);
    }
    cp_commit();
    if (tid < 128) *(float*)(smc + BIAS1 + tid * 4) = b_ih[n0 + tid] + b_hh[n0 + tid];
    cp_wait0();
    __syncthreads();

    const int wm = wid & 1, wn = wid >> 1;   // warp tile: m64 x n32
    float acc[4][4][4];
#pragma unroll
    for (int a = 0; a < 4; ++a)
#pragma unroll
        for (int b = 0; b < 4; ++b)
#pragma unroll
            for (int c = 0; c < 4; ++c) acc[a][b][c] = 0.0f;

    uint32_t aA = sb + XS1 + (uint32_t)((wm * 64 + (lane & 15)) * 272) + ((lane & 16) ? 16u : 0u);
    uint32_t aB = sb + WS1 + (uint32_t)((wn * 32 + (lane & 7)) * 272) + ((lane & 8) ? 16u : 0u);

#pragma unroll 2
    for (int k = 0; k < 8; ++k) {
        uint32_t ah[4][4], bh[4][2];
#pragma unroll
        for (int mj = 0; mj < 4; ++mj)
            LDSM_X4(ah[mj][0], ah[mj][1], ah[mj][2], ah[mj][3], aA + mj * 4352u);
#pragma unroll
        for (int nj = 0; nj < 4; ++nj)
            LDSM_X2(bh[nj][0], bh[nj][1], aB + nj * 2176u);
#pragma unroll
        for (int mj = 0; mj < 4; ++mj)
#pragma unroll
            for (int nj = 0; nj < 4; ++nj)
                MMA16816F16(acc[mj][nj], ah[mj][0], ah[mj][1], ah[mj][2], ah[mj][3], bh[nj][0], bh[nj][1]);
        aA += 32; aB += 32;
    }
    __syncthreads();   // tile reads done; D overlays x/W region

    float* Dsm = (float*)smc;
    {
        int rr = wm * 64 + (lane >> 2), cb = wn * 32 + (lane & 3) * 2;
#pragma unroll
        for (int mj = 0; mj < 4; ++mj)
#pragma unroll
            for (int nj = 0; nj < 4; ++nj) {
                *(float2*)&Dsm[(rr + mj * 16) * 132 + cb + nj * 8]     = make_float2(acc[mj][nj][0], acc[mj][nj][1]);
                *(float2*)&Dsm[(rr + mj * 16 + 8) * 132 + cb + nj * 8] = make_float2(acc[mj][nj][2], acc[mj][nj][3]);
            }
    }
    __syncthreads();

    const float* bias = (const float*)(smc + BIAS1);
#pragma unroll
    for (int i = 0; i < 16; ++i) {
        int o = tid + 256 * i;
        int row = o >> 5, q = o & 31;
        float vx = Dsm[row * 132 + q * 4]     + bias[q * 4];
        float vy = Dsm[row * 132 + q * 4 + 1] + bias[q * 4 + 1];
        float vz = Dsm[row * 132 + q * 4 + 2] + bias[q * 4 + 2];
        float vw = Dsm[row * 132 + q * 4 + 3] + bias[q * 4 + 3];
        int r = r0 + row;
        int b = r >> 10, tt = r & 1023;
        uint2 pack = make_uint2(pkh(vx, vy), pkh(vz, vw));
        *(uint2*)(g_xg + ((size_t)tt * BB + b) * G4 + n0 + q * 4) = pack;
    }
}

// ---------------------------------------------------------------------------
// Phase 2: persistent HMMA LSTM, all-fp16 single-plane operands.
// CTA bx: hs=bx&31 -> h-cols [16hs,+16); bg=bx>>5 -> batches [32bg,+32).
// D[32,64] = h . W^T, 1 MMA term. Warps 0-3 compute (warp = m16 x n32).
// Barrier: pre-sync + tid0 red.release; ALL threads acquire-poll, no post-sync.
__global__ void __launch_bounds__(256, 1)
lstm_mma(const float* __restrict__ W_hh) {
    extern __shared__ char smc[];
    const uint32_t sb = (uint32_t)__cvta_generic_to_shared(smc);
    const int tid = threadIdx.x, wid = tid >> 5, lane = tid & 31;
    const int hs = blockIdx.x & 31, bg = blockIdx.x >> 5;
    const int c0 = hs * 16, b0g = bg * 32;

    // ---- one-time W slice load -> fp16 (row n = gate(n>>4), col(n&15)) ----
    for (int p = tid; p < 64 * 256; p += 256) {
        int n = p >> 8, kw = p & 255, k = kw * 2;
        int grow = (n >> 4) * HH + c0 + (n & 15);
        float w0 = W_hh[(size_t)grow * HH + k];
        float w1 = W_hh[(size_t)grow * HH + k + 1];
        *(uint32_t*)(smc + WF + n * 1040 + kw * 4) = pkh(w0, w1);
    }
    __syncthreads();

    const int col = tid & 15, bt = tid >> 4;   // epilogue ownership
    float* Drow = (float*)(smc + DSM);
    int* const ctr = &g_ctr4[bg << 5];
    float cst[2] = {0.0f, 0.0f};

    // initial xg prefetch (t = 0)
    float xr[2][4], xn[2][4];
    {
        const __half* xgp = g_xg + (size_t)b0g * G4;
#pragma unroll
        for (int bi = 0; bi < 2; ++bi) {
            int l = bt + 16 * bi;
#pragma unroll
            for (int g = 0; g < 4; ++g)
                xr[bi][g] = __half2float(__ldcg(xgp + (size_t)l * G4 + g * HH + c0 + col));
        }
    }

    for (int t = 0; t < TT; ++t) {
        // ---- stage h(t) fp16 via cp.async (32 KB) ----
        const __half* hhp = g_hh[t & 1];
#pragma unroll
        for (int i = 0; i < 8; ++i) {
            int c = tid + 256 * i;              // [0,2048) 16B chunks
            int b = c >> 6, kc = c & 63;
            cp16(sb + HHI + (uint32_t)(b * 1040 + kc * 16),
                 hhp + (size_t)(b0g + b) * HH + kc * 8);
        }
        cp_commit();

        // ---- prefetch xg(t+1) while cp.async runs ----
        {
            int tn = (t + 1 < TT) ? t + 1 : t;
            const __half* xgp = g_xg + ((size_t)tn * BB + b0g) * G4;
#pragma unroll
            for (int bi = 0; bi < 2; ++bi) {
                int l = bt + 16 * bi;
#pragma unroll
                for (int g = 0; g < 4; ++g)
                    xn[bi][g] = __half2float(__ldcg(xgp + (size_t)l * G4 + g * HH + c0 + col));
            }
        }

        cp_wait0();
        __syncthreads();

        // ---- tensor-core loop: 4 compute warps, warp = m16(wm) x n32(wn) ----
        if (wid < 4) {
            const int wm = wid & 1, wn = wid >> 1;
            float acc[4][4];
#pragma unroll
            for (int a = 0; a < 4; ++a)
#pragma unroll
                for (int b = 0; b < 4; ++b) acc[a][b] = 0.0f;

            uint32_t aA = sb + HHI + (uint32_t)((wm * 16 + (lane & 15)) * 1040) + ((lane & 16) ? 16u : 0u);
            uint32_t aB = sb + WF + (uint32_t)((wn * 32 + (lane & 7)) * 1040) + (uint32_t)((lane >> 3) * 16);

#pragma unroll 4
            for (int k = 0; k < 16; ++k) {     // k32 blocks
                uint32_t ahA[4], ahB[4];
                LDSM_X4(ahA[0], ahA[1], ahA[2], ahA[3], aA);
                LDSM_X4(ahB[0], ahB[1], ahB[2], ahB[3], aA + 32u);
#pragma unroll
                for (int nj = 0; nj < 4; ++nj) {
                    uint32_t bh[4];
                    LDSM_X4(bh[0], bh[1], bh[2], bh[3], aB + nj * 8320u);
                    MMA16816F16(acc[nj], ahA[0], ahA[1], ahA[2], ahA[3], bh[0], bh[1]);
                    MMA16816F16(acc[nj], ahB[0], ahB[1], ahB[2], ahB[3], bh[2], bh[3]);
                }
                aA += 64; aB += 64;
            }
            int rr = wm * 16 + (lane >> 2), cb = wn * 32 + (lane & 3) * 2;
#pragma unroll
            for (int nj = 0; nj < 4; ++nj) {
                *(float2*)&Drow[rr * 68 + cb + nj * 8]       = make_float2(acc[nj][0], acc[nj][1]);
                *(float2*)&Drow[(rr + 8) * 68 + cb + nj * 8] = make_float2(acc[nj][2], acc[nj][3]);
            }
        }
        __syncthreads();

        // ---- cell update: thread owns col (c0+col), batches {bt, bt+16} ----
        __half* hhn = g_hh[(t + 1) & 1];
#pragma unroll
        for (int bi = 0; bi < 2; ++bi) {
            int l = bt + 16 * bi;
            float pi = Drow[l * 68 +  0 + col] + xr[bi][0];
            float pf = Drow[l * 68 + 16 + col] + xr[bi][1];
            float pg = Drow[l * 68 + 32 + col] + xr[bi][2];
            float po = Drow[l * 68 + 48 + col] + xr[bi][3];
            float ig = fsigmoid(pi);
            float fg = fsigmoid(pf);
            float gg = ftanh(pg);
            float og = fsigmoid(po);
            float c  = fg * cst[bi] + ig * gg;
            cst[bi] = c;
            float hv = og * ftanh(c);
            hhn[(size_t)(b0g + l) * HH + c0 + col] = __float2half_rn(hv);
        }
#pragma unroll
        for (int bi = 0; bi < 2; ++bi)
#pragma unroll
            for (int g = 0; g < 4; ++g) xr[bi][g] = xn[bi][g];

        // ---- per-group barrier: pre-sync orders h stores; tid0 releases; ALL
        //      threads acquire-poll independently (no post-barrier bar.sync) ----
        __syncthreads();
        if (tid == 0)
            asm volatile("red.release.gpu.global.add.s32 [%0], 1;" :: "l"(ctr) : "memory");
        {
            const int target = 32 * (t + 1);
            int v;
            do {
                asm volatile("ld.acquire.gpu.global.s32 %0, [%1];" : "=r"(v) : "l"(ctr) : "memory");
            } while (v < target);
        }
    }
}

// ---------------------------------------------------------------------------
// Phase 3: out[b] = sigmoid(h_last . W_fc + b_fc). t=1023 wrote plane 0.
__global__ void fc_out(const float* __restrict__ W_fc, const float* __restrict__ b_fc,
                       float* __restrict__ out) {
    __shared__ float red[128];
    const int b = blockIdx.x, tid = threadIdx.x;
    const __half* hh = g_hh[0] + b * HH;
    float s = 0.0f;
#pragma unroll
    for (int k = tid; k < HH; k += 128)
        s = fmaf(__half2float(hh[k]), W_fc[k], s);
    red[tid] = s;
    __syncthreads();
    for (int off = 64; off > 0; off >>= 1) {
        if (tid < off) red[tid] += red[tid + off];
        __syncthreads();
    }
    if (tid == 0) out[b] = 1.0f / (1.0f + expf(-(red[0] + b_fc[0])));
}

// ---------------------------------------------------------------------------
extern "C" void kernel_launch(void* const* d_in, const int* in_sizes, int n_in,
                              void* d_out, int out_size) {
    const float* x    = (const float*)d_in[0];
    const float* W_ih = (const float*)d_in[1];
    const float* W_hh = (const float*)d_in[2];
    const float* b_ih = (const float*)d_in[3];
    const float* b_hh = (const float*)d_in[4];
    const float* W_fc = (const float*)d_in[5];
    const float* b_fc = (const float*)d_in[6];
    float* out = (float*)d_out;

    cudaFuncSetAttribute(xg_hmma,  cudaFuncAttributeMaxDynamicSharedMemorySize, SMEM1_BYTES);
    cudaFuncSetAttribute(lstm_mma, cudaFuncAttributeMaxDynamicSharedMemorySize, SMEM_BYTES);

    init_state<<<256, 256>>>();
    cvt_in<<<(XF4 + WF4 + 255) / 256, 256>>>(x, W_ih);
    xg_hmma<<<dim3(1024, 16), 256, SMEM1_BYTES>>>(b_ih, b_hh);
    lstm_mma<<<NCTA, 256, SMEM_BYTES>>>(W_hh);
    fc_out<<<BB, 128>>>(W_fc, b_fc, out);
}